// round 8
// baseline (speedup 1.0000x reference)
#include <cuda_runtime.h>
#include <math.h>

// Shapes (fixed): N=64, T=300, V=25, C=64, K=3, F=64, I=16, d=T*I=4800
#define SCALE_D 0.014433756729740645f   // 1/sqrt(4800)

typedef unsigned long long u64;

__device__ __forceinline__ void up2(u64 v, float& a, float& b) {
    asm("mov.b64 {%0, %1}, %2;" : "=f"(a), "=f"(b) : "l"(v));
}
__device__ __forceinline__ void fma2(u64& d, u64 a, u64 b) {
    asm("fma.rn.f32x2 %0, %1, %2, %0;" : "+l"(d) : "l"(a), "l"(b));
}

// Scratch (module-static device memory; no runtime allocation)
__device__ float g_Spart[30 * 3 * 64 * 625];   // [chunk][k][n][v*25+w] partial scores
__device__ float g_Aad[3 * 64 * 625];          // A_adapt [k][n][v*25+w]

// ---------------------------------------------------------------------------
// Kernel 1: attention score partials. Grid (30, 64), 256 threads.
// X stored DUPLICATED in smem (Xd): LDS.128 -> (x,x,x',x') = 2 packed u64
// broadcast operands, zero MOVs. Embedding GEMM runs on FFMA2.
// Score accumulation phase: R4 scalar float4 form (known good).
// ---------------------------------------------------------------------------
__global__ __launch_bounds__(256) void score_kernel(
    const float* __restrict__ x,
    const float* __restrict__ Wq, const float* __restrict__ bq,
    const float* __restrict__ Wk, const float* __restrict__ bk)
{
    extern __shared__ float sm[];
    float* Gs = sm;            // [64][96] combined Wq|Wk (j<48 Q, j>=48 K)
    float* bs = Gs + 6144;     // [96]
    float* Xd = bs + 96;       // [2][25][132] duplicated X = 6600
    float* Qt = Xd + 6600;     // [2][3][16][28] = 2688 (i-major, v contiguous)
    float* Kt = Qt + 2688;     // [2][3][16][28] = 2688, +8 pad
    // total 18224 floats = 72896 B

    const int tid = threadIdx.x;
    const int chunk = blockIdx.x;
    const int n = blockIdx.y;

    // Load combined embedding weights into smem
    for (int e = tid; e < 6144; e += 256) {
        int c = e / 96, j = e % 96;
        float v;
        if (j < 48)  v = Wq[(j >> 4) * 1024 + c * 16 + (j & 15)];
        else { int jj = j - 48; v = Wk[(jj >> 4) * 1024 + c * 16 + (jj & 15)]; }
        Gs[e] = v;
    }
    if (tid < 96) bs[tid] = (tid < 48) ? bq[tid] : bk[tid - 48];
    if (tid < 8) Kt[2688 + tid] = 0.f;   // pad after Kt (w4=6 overread)

    // Score-phase task decode: 147 tasks = 3 kq x 7 w4 x 7 vp (4v x 4w tiles)
    const int kq_s = tid / 49;
    const int rs   = tid % 49;
    const int w4_s = rs / 7;
    const int vp_s = rs % 7;
    const bool score_active = (tid < 147);

    float acc[4][4];
#pragma unroll
    for (int a = 0; a < 4; a++)
#pragma unroll
        for (int b2 = 0; b2 < 4; b2++) acc[a][b2] = 0.f;

    const float* xn = x + (n * 300 + chunk * 10) * 1600;

    // Embedding task decode (240 active)
    const int t2   = tid / 120;
    const int re   = tid % 120;
    const int qk   = re / 60;
    const int r2   = re % 60;
    const int rowg = r2 / 12;
    const int ic   = r2 % 12;
    const int kq_e = ic >> 2;
    const int i4   = ic & 3;
    const int gcol = qk * 12 + kq_e * 4 + i4;

    for (int step = 0; step < 5; ++step) {
        __syncthreads();
        {   // load 2 consecutive t tiles (800 float4), write DUPLICATED
            const float4* src = (const float4*)(xn + step * 3200);
            for (int e = tid; e < 800; e += 256) {
                float4 v = src[e];
                int tile = e / 400, er = e % 400;
                int row = er >> 4, cq = er & 15;
                float* d = Xd + tile * 3300 + row * 132 + cq * 8;
                *(float4*)(d)     = make_float4(v.x, v.x, v.y, v.y);
                *(float4*)(d + 4) = make_float4(v.z, v.z, v.w, v.w);
            }
        }
        __syncthreads();

        // --- Q/K embedding GEMM: E = X * [Wq|Wk] + bias, FFMA2, 240 tasks ---
        if (tid < 240) {
            u64 acc01[5], acc23[5];
#pragma unroll
            for (int rr = 0; rr < 5; rr++) { acc01[rr] = 0ull; acc23[rr] = 0ull; }

            const float* Xb = Xd + t2 * 3300 + rowg * 660;   // 5 rows * 132
            const ulonglong2* G2 = (const ulonglong2*)Gs;    // row = 24 ull2
#pragma unroll 4
            for (int cp = 0; cp < 32; ++cp) {
                ulonglong2 xp[5];
#pragma unroll
                for (int rr = 0; rr < 5; ++rr)
                    xp[rr] = *(const ulonglong2*)(Xb + rr * 132 + cp * 4);
                ulonglong2 g0 = G2[(2 * cp) * 24 + gcol];
                ulonglong2 g1 = G2[(2 * cp + 1) * 24 + gcol];
#pragma unroll
                for (int rr = 0; rr < 5; ++rr) {
                    fma2(acc01[rr], xp[rr].x, g0.x);
                    fma2(acc23[rr], xp[rr].x, g0.y);
                    fma2(acc01[rr], xp[rr].y, g1.x);
                    fma2(acc23[rr], xp[rr].y, g1.y);
                }
            }
            const int bb0 = qk * 48 + kq_e * 16 + i4 * 4;
            const float b0 = bs[bb0], b1 = bs[bb0 + 1], b2 = bs[bb0 + 2], b3 = bs[bb0 + 3];
            float* eb = (qk ? Kt : Qt) + t2 * 1344 + kq_e * 448 + (i4 * 4) * 28;
#pragma unroll
            for (int rr = 0; rr < 5; ++rr) {
                int row = rowg * 5 + rr;
                float e0, e1, e2, e3;
                up2(acc01[rr], e0, e1);
                up2(acc23[rr], e2, e3);
                eb[row]      = e0 + b0;
                eb[28 + row] = e1 + b1;
                eb[56 + row] = e2 + b2;
                eb[84 + row] = e3 + b3;
            }
        }
        __syncthreads();

        // --- Score accumulation: S[k][4v][4w] += Q^T.K over i=16, 2 t's ---
        if (score_active) {
#pragma unroll
            for (int ti = 0; ti < 2; ++ti) {
                const float4* qv = (const float4*)(Qt + ti * 1344 + kq_s * 448 + vp_s * 4);
                const float4* kt = (const float4*)(Kt + ti * 1344 + kq_s * 448 + w4_s * 4);
#pragma unroll
                for (int i = 0; i < 16; ++i) {
                    float4 q  = qv[i * 7];
                    float4 kv = kt[i * 7];
                    acc[0][0] += q.x * kv.x; acc[0][1] += q.x * kv.y;
                    acc[0][2] += q.x * kv.z; acc[0][3] += q.x * kv.w;
                    acc[1][0] += q.y * kv.x; acc[1][1] += q.y * kv.y;
                    acc[1][2] += q.y * kv.z; acc[1][3] += q.y * kv.w;
                    acc[2][0] += q.z * kv.x; acc[2][1] += q.z * kv.y;
                    acc[2][2] += q.z * kv.z; acc[2][3] += q.z * kv.w;
                    acc[3][0] += q.w * kv.x; acc[3][1] += q.w * kv.y;
                    acc[3][2] += q.w * kv.z; acc[3][3] += q.w * kv.w;
                }
            }
        }
    }

    // --- write chunk partials (guards discard the pad-lane garbage) ---
    if (score_active) {
        float* base = g_Spart + ((chunk * 3 + kq_s) * 64 + n) * 625;
#pragma unroll
        for (int vi = 0; vi < 4; ++vi) {
            int v = vp_s * 4 + vi;
            if (v < 25) {
#pragma unroll
                for (int j = 0; j < 4; ++j) {
                    int w = w4_s * 4 + j;
                    if (w < 25) base[v * 25 + w] = acc[vi][j];
                }
            }
        }
    }
}

// ---------------------------------------------------------------------------
// Kernel 2: reduce chunk partials (deterministic order), softmax, add A.
// ---------------------------------------------------------------------------
__global__ __launch_bounds__(128) void softmax_kernel(const float* __restrict__ A)
{
    __shared__ float S[625];
    const int b = blockIdx.x;
    const int kq = b / 64, n = b % 64;
    const int tid = threadIdx.x;

    for (int e = tid; e < 625; e += 128) {
        float s = 0.f;
        int base = ((kq * 64) + n) * 625 + e;
#pragma unroll 6
        for (int ch = 0; ch < 30; ++ch) s += g_Spart[ch * 120000 + base];
        S[e] = s;
    }
    __syncthreads();

    if (tid < 25) {
        const int v = tid;
        float m = -1e30f;
#pragma unroll
        for (int w = 0; w < 25; ++w) {
            float z = S[v * 25 + w] * SCALE_D;
            m = fmaxf(m, z);
        }
        float p[25];
        float sum = 0.f;
#pragma unroll
        for (int w = 0; w < 25; ++w) {
            p[w] = expf(S[v * 25 + w] * SCALE_D - m);
            sum += p[w];
        }
        float inv = 1.f / sum;
        float* dst = g_Aad + ((kq * 64) + n) * 625 + v * 25;
        const float* Ab = A + kq * 625 + v * 25;
#pragma unroll
        for (int w = 0; w < 25; ++w) dst[w] = Ab[w] + p[w] * inv;
    }
}

// ---------------------------------------------------------------------------
// Kernel 3: main path. Grid (25, 64), 256 threads.
// H = X*W on FFMA2 via duplicated-X (Xd); Y = A^T H on FFMA2 via duplicated-A
// (Adup) + natural u64 H f-pairs. Y split over 2 v-halves, smem combine.
// ---------------------------------------------------------------------------
__global__ __launch_bounds__(256) void main_kernel(
    const float* __restrict__ x, const float* __restrict__ W,
    const float* __restrict__ b, float* __restrict__ y)
{
    extern __shared__ float sm[];
    float* Ws    = sm;             // [64][192] = 12288
    float* Xd    = Ws + 12288;     // [25][132] duplicated = 3300
    float* Hs    = Xd + 3300;      // [25][192] = 4800
    float* ybias = Hs + 4800;      // [25][64]  = 1600
    float* Adup  = ybias + 1600;   // [3][25][56] duplicated+pad = 4200
    float* csum  = Adup + 4200;    // [3][25]+pad = 80
    float* stg   = csum + 80;      // [112][16] staging = 1792
    // total 28060 floats = 112240 B

    const int tid = threadIdx.x;
    const int n = blockIdx.y;
    const int tc = blockIdx.x;

    {   // load W (contiguous)
        const float4* src = (const float4*)W;
        float4* dst = (float4*)Ws;
        for (int e = tid; e < 3072; e += 256) dst[e] = src[e];
    }
    // load A_adapt for this n, store DUPLICATED with row stride 56
    for (int e = tid; e < 1875; e += 256) {
        int k = e / 625, rem = e % 625;
        int v = rem / 25, w = rem % 25;
        float a = g_Aad[(k * 64 + n) * 625 + rem];
        float* d = Adup + k * 1400 + v * 56 + 2 * w;
        d[0] = a; d[1] = a;
    }
    // zero the w=25..27 duplicated pad (floats 50..55 of each row)
    for (int e = tid; e < 450; e += 256) {
        int k = e / 150, r = e % 150;
        Adup[k * 1400 + (r / 6) * 56 + 50 + (r % 6)] = 0.f;
    }
    __syncthreads();

    if (tid < 75) {
        int k = tid / 25, w = tid % 25;
        float s = 0.f;
#pragma unroll
        for (int v = 0; v < 25; ++v) s += Adup[k * 1400 + v * 56 + 2 * w];
        csum[tid] = s;
    }
    __syncthreads();
    for (int e = tid; e < 1600; e += 256) {
        int w = e / 64, f = e % 64;
        ybias[e] = b[f] * csum[w] + b[64 + f] * csum[25 + w] + b[128 + f] * csum[50 + w];
    }

    const int col4 = tid % 48;      // H phase (tid < 240)
    const int rowg = tid / 48;
    const int ytile = tid % 112;    // Y phase (tid < 224)
    const int vh = tid / 112;       // v-half: 0 -> v 0..12, 1 -> v 13..24
    const int w4 = ytile / 16;      // 0..6 (w quad)
    const int f4 = ytile % 16;      // 0..15

    for (int tt = 0; tt < 12; ++tt) {
        const int t = tc * 12 + tt;
        __syncthreads();
        {   // load X tile (400 float4), write DUPLICATED (stride 132)
            const float4* src = (const float4*)(x + (n * 300 + t) * 1600);
            for (int e = tid; e < 400; e += 256) {
                float4 v = src[e];
                int row = e >> 4, cq = e & 15;
                float* d = Xd + row * 132 + cq * 8;
                *(float4*)(d)     = make_float4(v.x, v.x, v.y, v.y);
                *(float4*)(d + 4) = make_float4(v.z, v.z, v.w, v.w);
            }
        }
        __syncthreads();

        // --- H = X * W : 25x192, 5 rows x 4 cols, FFMA2 via Xd ---
        if (tid < 240) {
            u64 acc01[5], acc23[5];
#pragma unroll
            for (int r = 0; r < 5; ++r) { acc01[r] = 0ull; acc23[r] = 0ull; }
            const float* Xb = Xd + rowg * 660;               // 5 rows * 132
            const ulonglong2* W2 = (const ulonglong2*)Ws;    // row = 48 ull2
#pragma unroll 4
            for (int cp = 0; cp < 32; ++cp) {
                ulonglong2 xp[5];
#pragma unroll
                for (int r = 0; r < 5; ++r)
                    xp[r] = *(const ulonglong2*)(Xb + r * 132 + cp * 4);
                ulonglong2 w0 = W2[(2 * cp) * 48 + col4];
                ulonglong2 w1 = W2[(2 * cp + 1) * 48 + col4];
#pragma unroll
                for (int r = 0; r < 5; ++r) {
                    fma2(acc01[r], xp[r].x, w0.x);
                    fma2(acc23[r], xp[r].x, w0.y);
                    fma2(acc01[r], xp[r].y, w1.x);
                    fma2(acc23[r], xp[r].y, w1.y);
                }
            }
            float4* H4 = (float4*)Hs;
#pragma unroll
            for (int r = 0; r < 5; ++r) {
                float h0, h1, h2, h3;
                up2(acc01[r], h0, h1);
                up2(acc23[r], h2, h3);
                H4[(rowg * 5 + r) * 48 + col4] = make_float4(h0, h1, h2, h3);
            }
        }
        __syncthreads();

        // --- Y: 4w x 4f tiles over 2 v-halves, FFMA2 via Adup + H pairs ---
        u64 s2[4][2];
        if (tid < 224) {
            const ulonglong2* yb2 = (const ulonglong2*)ybias;  // row = 16 ull2
#pragma unroll
            for (int j = 0; j < 4; ++j) {
                int w = w4 * 4 + j;
                if (vh == 0 && w < 25) {
                    ulonglong2 yv = yb2[w * 16 + f4];
                    s2[j][0] = yv.x; s2[j][1] = yv.y;
                } else {
                    s2[j][0] = 0ull; s2[j][1] = 0ull;
                }
            }
            const int vbeg = vh ? 13 : 0;
            const int vend = vh ? 25 : 13;
            const ulonglong2* H2 = (const ulonglong2*)Hs;      // row = 48 ull2
#pragma unroll
            for (int k = 0; k < 3; ++k) {
                const float* Ab = Adup + k * 1400 + w4 * 8;
                const int hidx = k * 16 + f4;                  // ull2 col in Hs row
                for (int v = vbeg; v < vend; ++v) {
                    ulonglong2 h = H2[v * 48 + hidx];
                    ulonglong2 a01 = *(const ulonglong2*)(Ab + v * 56);
                    ulonglong2 a23 = *(const ulonglong2*)(Ab + v * 56 + 4);
                    fma2(s2[0][0], a01.x, h.x); fma2(s2[0][1], a01.x, h.y);
                    fma2(s2[1][0], a01.y, h.x); fma2(s2[1][1], a01.y, h.y);
                    fma2(s2[2][0], a23.x, h.x); fma2(s2[2][1], a23.x, h.y);
                    fma2(s2[3][0], a23.y, h.x); fma2(s2[3][1], a23.y, h.y);
                }
            }
        }
        if (tid < 224 && vh == 1) {      // stage upper-half partials
            u64* st = (u64*)stg;
#pragma unroll
            for (int j = 0; j < 4; ++j) {
                st[ytile * 8 + j * 2]     = s2[j][0];
                st[ytile * 8 + j * 2 + 1] = s2[j][1];
            }
        }
        __syncthreads();
        if (tid < 224 && vh == 0) {
            const u64* st = (const u64*)stg;
            float4* yout = (float4*)(y + (n * 300 + t) * 1600);
#pragma unroll
            for (int j = 0; j < 4; ++j) {
                int w = w4 * 4 + j;
                if (w < 25) {
                    float p0, p1, p2, p3, o0, o1, o2, o3;
                    up2(s2[j][0], p0, p1);
                    up2(s2[j][1], p2, p3);
                    up2(st[ytile * 8 + j * 2],     o0, o1);
                    up2(st[ytile * 8 + j * 2 + 1], o2, o3);
                    yout[w * 16 + f4] = make_float4(p0 + o0, p1 + o1, p2 + o2, p3 + o3);
                }
            }
        }
    }
}

// ---------------------------------------------------------------------------
extern "C" void kernel_launch(void* const* d_in, const int* in_sizes, int n_in,
                              void* d_out, int out_size)
{
    const float* x  = (const float*)d_in[0];
    const float* A  = (const float*)d_in[1];
    const float* W  = (const float*)d_in[2];
    const float* b  = (const float*)d_in[3];
    const float* Wq = (const float*)d_in[4];
    const float* bq = (const float*)d_in[5];
    const float* Wk = (const float*)d_in[6];
    const float* bk = (const float*)d_in[7];
    float* y = (float*)d_out;

    const int score_smem = 18224 * 4;   // 72896 B
    const int main_smem  = 28060 * 4;   // 112240 B
    cudaFuncSetAttribute(score_kernel, cudaFuncAttributeMaxDynamicSharedMemorySize, score_smem);
    cudaFuncSetAttribute(main_kernel,  cudaFuncAttributeMaxDynamicSharedMemorySize, main_smem);

    score_kernel<<<dim3(30, 64), 256, score_smem>>>(x, Wq, bq, Wk, bk);
    softmax_kernel<<<192, 128>>>(A);
    main_kernel<<<dim3(25, 64), 256, main_smem>>>(x, W, b, y);
}

// round 9
// speedup vs baseline: 1.1468x; 1.1468x over previous
#include <cuda_runtime.h>
#include <math.h>

// Shapes (fixed): N=64, T=300, V=25, C=64, K=3, F=64, I=16, d=T*I=4800
#define SCALE_D 0.014433756729740645f   // 1/sqrt(4800)

typedef unsigned long long u64;

__device__ __forceinline__ u64 pk2(float lo, float hi) {
    u64 r; asm("mov.b64 %0, {%1, %2};" : "=l"(r) : "f"(lo), "f"(hi)); return r;
}
__device__ __forceinline__ void up2(u64 v, float& a, float& b) {
    asm("mov.b64 {%0, %1}, %2;" : "=f"(a), "=f"(b) : "l"(v));
}
__device__ __forceinline__ void fma2(u64& d, u64 a, u64 b) {
    asm("fma.rn.f32x2 %0, %1, %2, %0;" : "+l"(d) : "l"(a), "l"(b));
}

// Scratch (module-static device memory; no runtime allocation)
__device__ float g_Spart[30 * 3 * 64 * 625];   // [chunk][k][n][v*25+w] partial scores
__device__ float g_Aad[3 * 64 * 625];          // A_adapt [k][n][v*25+w]

// ---------------------------------------------------------------------------
// Kernel 1: attention score partials. EXACT copy of the R5 version (231 us).
// ---------------------------------------------------------------------------
__global__ __launch_bounds__(256) void score_kernel(
    const float* __restrict__ x,
    const float* __restrict__ Wq, const float* __restrict__ bq,
    const float* __restrict__ Wk, const float* __restrict__ bk)
{
    extern __shared__ float sm[];
    float* Gs = sm;            // [64][96] combined Wq|Wk (j<48 Q, j>=48 K)
    float* bs = Gs + 6144;     // [96]
    float* Xs = bs + 96;       // [2][25][68] padded = 3400
    float* Qt = Xs + 3400;     // [2][3][16][28] = 2688 (i-major, v contiguous)
    float* Kt = Qt + 2688;     // [2][3][16][28] = 2688
    // total 15016 floats = 60064 B

    const int tid = threadIdx.x;
    const int chunk = blockIdx.x;
    const int n = blockIdx.y;

    for (int e = tid; e < 6144; e += 256) {
        int c = e / 96, j = e % 96;
        float v;
        if (j < 48)  v = Wq[(j >> 4) * 1024 + c * 16 + (j & 15)];
        else { int jj = j - 48; v = Wk[(jj >> 4) * 1024 + c * 16 + (jj & 15)]; }
        Gs[e] = v;
    }
    if (tid < 96) bs[tid] = (tid < 48) ? bq[tid] : bk[tid - 48];

    const int kq_s = tid / 49;
    const int rs   = tid % 49;
    const int w4_s = rs / 7;
    const int vp_s = rs % 7;
    const bool score_active = (tid < 147);

    float acc[4][4];
#pragma unroll
    for (int a = 0; a < 4; a++)
#pragma unroll
        for (int b2 = 0; b2 < 4; b2++) acc[a][b2] = 0.f;

    const float* xn = x + (n * 300 + chunk * 10) * 1600;

    const int t2   = tid / 120;
    const int re   = tid % 120;
    const int qk   = re / 60;
    const int r2   = re % 60;
    const int rowg = r2 / 12;
    const int ic   = r2 % 12;
    const int kq_e = ic >> 2;
    const int i4   = ic & 3;
    const int gcol = qk * 12 + kq_e * 4 + i4;

    for (int step = 0; step < 5; ++step) {
        __syncthreads();
        {
            const float4* src = (const float4*)(xn + step * 3200);
            float4* dst = (float4*)Xs;
            for (int e = tid; e < 800; e += 256) {
                int tile = e / 400, er = e % 400;
                int row = er >> 4, col = er & 15;
                dst[tile * 425 + row * 17 + col] = src[e];
            }
        }
        __syncthreads();

        if (tid < 240) {
            float a0[5], a1[5], a2[5], a3[5];
#pragma unroll
            for (int rr = 0; rr < 5; rr++) { a0[rr] = a1[rr] = a2[rr] = a3[rr] = 0.f; }

            const float* Xb = Xs + t2 * 1700 + rowg * 340;
            const float4* G4 = (const float4*)Gs;
#pragma unroll 4
            for (int c4 = 0; c4 < 16; ++c4) {
                float4 xr[5];
#pragma unroll
                for (int rr = 0; rr < 5; ++rr)
                    xr[rr] = *(const float4*)(Xb + rr * 68 + c4 * 4);
#pragma unroll
                for (int j = 0; j < 4; ++j) {
                    float4 g = G4[(c4 * 4 + j) * 24 + gcol];
#pragma unroll
                    for (int rr = 0; rr < 5; ++rr) {
                        float xv = (j == 0) ? xr[rr].x : (j == 1) ? xr[rr].y
                                 : (j == 2) ? xr[rr].z : xr[rr].w;
                        a0[rr] += xv * g.x; a1[rr] += xv * g.y;
                        a2[rr] += xv * g.z; a3[rr] += xv * g.w;
                    }
                }
            }
            const int bb0 = qk * 48 + kq_e * 16 + i4 * 4;
            const float b0 = bs[bb0], b1 = bs[bb0 + 1], b2 = bs[bb0 + 2], b3 = bs[bb0 + 3];
            float* eb = (qk ? Kt : Qt) + t2 * 1344 + kq_e * 448 + (i4 * 4) * 28;
#pragma unroll
            for (int rr = 0; rr < 5; ++rr) {
                int row = rowg * 5 + rr;
                eb[row]      = a0[rr] + b0;
                eb[28 + row] = a1[rr] + b1;
                eb[56 + row] = a2[rr] + b2;
                eb[84 + row] = a3[rr] + b3;
            }
        }
        __syncthreads();

        if (score_active) {
#pragma unroll
            for (int ti = 0; ti < 2; ++ti) {
                const float4* qv = (const float4*)(Qt + ti * 1344 + kq_s * 448 + vp_s * 4);
                const float4* kt = (const float4*)(Kt + ti * 1344 + kq_s * 448 + w4_s * 4);
#pragma unroll
                for (int i = 0; i < 16; ++i) {
                    float4 q  = qv[i * 7];
                    float4 kv = kt[i * 7];
                    acc[0][0] += q.x * kv.x; acc[0][1] += q.x * kv.y;
                    acc[0][2] += q.x * kv.z; acc[0][3] += q.x * kv.w;
                    acc[1][0] += q.y * kv.x; acc[1][1] += q.y * kv.y;
                    acc[1][2] += q.y * kv.z; acc[1][3] += q.y * kv.w;
                    acc[2][0] += q.z * kv.x; acc[2][1] += q.z * kv.y;
                    acc[2][2] += q.z * kv.z; acc[2][3] += q.z * kv.w;
                    acc[3][0] += q.w * kv.x; acc[3][1] += q.w * kv.y;
                    acc[3][2] += q.w * kv.z; acc[3][3] += q.w * kv.w;
                }
            }
        }
    }

    if (score_active) {
        float* base = g_Spart + ((chunk * 3 + kq_s) * 64 + n) * 625;
#pragma unroll
        for (int vi = 0; vi < 4; ++vi) {
            int v = vp_s * 4 + vi;
            if (v < 25) {
#pragma unroll
                for (int j = 0; j < 4; ++j) {
                    int w = w4_s * 4 + j;
                    if (w < 25) base[v * 25 + w] = acc[vi][j];
                }
            }
        }
    }
}

// ---------------------------------------------------------------------------
// Kernel 2: reduce chunk partials (deterministic order), softmax, add A.
// ---------------------------------------------------------------------------
__global__ __launch_bounds__(128) void softmax_kernel(const float* __restrict__ A)
{
    __shared__ float S[625];
    const int b = blockIdx.x;
    const int kq = b / 64, n = b % 64;
    const int tid = threadIdx.x;

    for (int e = tid; e < 625; e += 128) {
        float s = 0.f;
        int base = ((kq * 64) + n) * 625 + e;
#pragma unroll 6
        for (int ch = 0; ch < 30; ++ch) s += g_Spart[ch * 120000 + base];
        S[e] = s;
    }
    __syncthreads();

    if (tid < 25) {
        const int v = tid;
        float m = -1e30f;
#pragma unroll
        for (int w = 0; w < 25; ++w) {
            float z = S[v * 25 + w] * SCALE_D;
            m = fmaxf(m, z);
        }
        float p[25];
        float sum = 0.f;
#pragma unroll
        for (int w = 0; w < 25; ++w) {
            p[w] = expf(S[v * 25 + w] * SCALE_D - m);
            sum += p[w];
        }
        float inv = 1.f / sum;
        float* dst = g_Aad + ((kq * 64) + n) * 625 + v * 25;
        const float* Ab = A + kq * 625 + v * 25;
#pragma unroll
        for (int w = 0; w < 25; ++w) dst[w] = Ab[w] + p[w] * inv;
    }
}

// ---------------------------------------------------------------------------
// Kernel 3: main path. Grid (25, 64), 256 threads.
// H = X*W scalar (R4 form, known good). Y batches 2 t's per pass: A loaded
// once per (k,v) for both t's (1.5 B/FMA), FFMA2 on f-pairs. ybias in regs.
// ---------------------------------------------------------------------------
__global__ __launch_bounds__(256) void main_kernel(
    const float* __restrict__ x, const float* __restrict__ W,
    const float* __restrict__ b, float* __restrict__ y)
{
    extern __shared__ float sm[];
    float* Ws   = sm;             // [64][192] = 12288
    float* Xs   = Ws + 12288;     // [2][25][68] = 3400
    float* Hs   = Xs + 3400;      // [2][25][192] = 9600
    float* As   = Hs + 9600;      // [3][25][28] padded = 2100
    float* csum = As + 2100;      // [3][25]+pad = 80
    float* bsm  = csum + 80;      // [192]
    // total 27660 floats = 110640 B -> 2 blocks/SM

    const int tid = threadIdx.x;
    const int n = blockIdx.y;
    const int tc = blockIdx.x;

    {   // load W (contiguous)
        const float4* src = (const float4*)W;
        float4* dst = (float4*)Ws;
        for (int e = tid; e < 3072; e += 256) dst[e] = src[e];
    }
    // load A_adapt for this n, repack to row stride 28
    for (int e = tid; e < 1875; e += 256) {
        int k = e / 625, rem = e % 625;
        int v = rem / 25, w = rem % 25;
        As[k * 700 + v * 28 + w] = g_Aad[(k * 64 + n) * 625 + rem];
    }
    // zero the w=25..27 pad columns
    for (int e = tid; e < 225; e += 256) {
        int k = e / 75, r = e % 75;
        As[k * 700 + (r / 3) * 28 + 25 + (r % 3)] = 0.f;
    }
    if (tid < 192) bsm[tid] = b[tid];
    __syncthreads();

    if (tid < 75) {
        int k = tid / 25, w = tid % 25;
        float s = 0.f;
#pragma unroll
        for (int v = 0; v < 25; ++v) s += As[k * 700 + v * 28 + w];
        csum[tid] = s;
    }
    __syncthreads();

    const int col4 = tid % 48;      // H phase (tid < 240)
    const int rowg = tid / 48;
    const int w4 = tid / 16;        // Y phase (tid < 112): w quad 0..6
    const int f4 = tid % 16;        // f quad 0..15

    // t-invariant bias accumulator seeds (Y threads only)
    u64 yb[4][2];
    if (tid < 112) {
#pragma unroll
        for (int j = 0; j < 4; ++j) {
            int w = w4 * 4 + j;
            if (w < 25) {
#pragma unroll
                for (int p = 0; p < 2; ++p) {
                    int f0 = f4 * 4 + 2 * p;
                    float v0 = bsm[f0]     * csum[w]      + bsm[64 + f0]     * csum[25 + w]
                             + bsm[128 + f0]     * csum[50 + w];
                    float v1 = bsm[f0 + 1] * csum[w]      + bsm[64 + f0 + 1] * csum[25 + w]
                             + bsm[128 + f0 + 1] * csum[50 + w];
                    yb[j][p] = pk2(v0, v1);
                }
            } else { yb[j][0] = 0ull; yb[j][1] = 0ull; }
        }
    }

    for (int g = 0; g < 6; ++g) {
        const int t0 = tc * 12 + g * 2;
        __syncthreads();
        {   // load 2 X tiles (800 float4), remap rows to stride 68
            const float4* src = (const float4*)(x + (n * 300 + t0) * 1600);
            float4* dst = (float4*)Xs;
            for (int e = tid; e < 800; e += 256) {
                int tile = e / 400, er = e % 400;
                int row = er >> 4, col = er & 15;
                dst[tile * 425 + row * 17 + col] = src[e];
            }
        }
        __syncthreads();

        // --- H = X * W for both t's: 25x192 each, 5r x 4c scalar tiles ---
        if (tid < 240) {
#pragma unroll
            for (int tt = 0; tt < 2; ++tt) {
                float a0[5], a1[5], a2[5], a3[5];
#pragma unroll
                for (int r = 0; r < 5; ++r) { a0[r] = a1[r] = a2[r] = a3[r] = 0.f; }
                const float* Xb = Xs + tt * 1700 + rowg * 340;
                const float4* W4 = (const float4*)Ws;
#pragma unroll 4
                for (int c4 = 0; c4 < 16; ++c4) {
                    float4 xr[5];
#pragma unroll
                    for (int r = 0; r < 5; ++r)
                        xr[r] = *(const float4*)(Xb + r * 68 + c4 * 4);
#pragma unroll
                    for (int j = 0; j < 4; ++j) {
                        float4 wv = W4[(c4 * 4 + j) * 48 + col4];
#pragma unroll
                        for (int r = 0; r < 5; ++r) {
                            float xv = (j == 0) ? xr[r].x : (j == 1) ? xr[r].y
                                     : (j == 2) ? xr[r].z : xr[r].w;
                            a0[r] += xv * wv.x; a1[r] += xv * wv.y;
                            a2[r] += xv * wv.z; a3[r] += xv * wv.w;
                        }
                    }
                }
                float4* H4 = (float4*)(Hs + tt * 4800);
#pragma unroll
                for (int r = 0; r < 5; ++r)
                    H4[(rowg * 5 + r) * 48 + col4] = make_float4(a0[r], a1[r], a2[r], a3[r]);
            }
        }
        __syncthreads();

        // --- Y: 4w x 4f x 2t tiles, 112 threads, A loaded once per (k,v) ---
        if (tid < 112) {
            u64 s2[2][4][2];
#pragma unroll
            for (int tt = 0; tt < 2; ++tt)
#pragma unroll
                for (int j = 0; j < 4; ++j) {
                    s2[tt][j][0] = yb[j][0];
                    s2[tt][j][1] = yb[j][1];
                }
            const ulonglong2* H2 = (const ulonglong2*)Hs;   // t block = 1200 ull2
#pragma unroll
            for (int k = 0; k < 3; ++k) {
                const float* Ab = As + k * 700 + w4 * 4;
                const int hidx = k * 16 + f4;                // ull2 col in H row
#pragma unroll 5
                for (int v = 0; v < 25; ++v) {
                    float4 a = *(const float4*)(Ab + v * 28);
                    u64 d0 = pk2(a.x, a.x), d1 = pk2(a.y, a.y);
                    u64 d2 = pk2(a.z, a.z), d3 = pk2(a.w, a.w);
                    ulonglong2 h0 = H2[v * 48 + hidx];
                    ulonglong2 h1 = H2[1200 + v * 48 + hidx];
                    fma2(s2[0][0][0], d0, h0.x); fma2(s2[0][0][1], d0, h0.y);
                    fma2(s2[0][1][0], d1, h0.x); fma2(s2[0][1][1], d1, h0.y);
                    fma2(s2[0][2][0], d2, h0.x); fma2(s2[0][2][1], d2, h0.y);
                    fma2(s2[0][3][0], d3, h0.x); fma2(s2[0][3][1], d3, h0.y);
                    fma2(s2[1][0][0], d0, h1.x); fma2(s2[1][0][1], d0, h1.y);
                    fma2(s2[1][1][0], d1, h1.x); fma2(s2[1][1][1], d1, h1.y);
                    fma2(s2[1][2][0], d2, h1.x); fma2(s2[1][2][1], d2, h1.y);
                    fma2(s2[1][3][0], d3, h1.x); fma2(s2[1][3][1], d3, h1.y);
                }
            }
#pragma unroll
            for (int tt = 0; tt < 2; ++tt) {
                float4* yout = (float4*)(y + (n * 300 + t0 + tt) * 1600);
#pragma unroll
                for (int j = 0; j < 4; ++j) {
                    int w = w4 * 4 + j;
                    if (w < 25) {
                        float p0, p1, p2, p3;
                        up2(s2[tt][j][0], p0, p1);
                        up2(s2[tt][j][1], p2, p3);
                        yout[w * 16 + f4] = make_float4(p0, p1, p2, p3);
                    }
                }
            }
        }
    }
}

// ---------------------------------------------------------------------------
extern "C" void kernel_launch(void* const* d_in, const int* in_sizes, int n_in,
                              void* d_out, int out_size)
{
    const float* x  = (const float*)d_in[0];
    const float* A  = (const float*)d_in[1];
    const float* W  = (const float*)d_in[2];
    const float* b  = (const float*)d_in[3];
    const float* Wq = (const float*)d_in[4];
    const float* bq = (const float*)d_in[5];
    const float* Wk = (const float*)d_in[6];
    const float* bk = (const float*)d_in[7];
    float* y = (float*)d_out;

    const int score_smem = 15016 * 4;   // 60064 B
    const int main_smem  = 27660 * 4;   // 110640 B
    cudaFuncSetAttribute(score_kernel, cudaFuncAttributeMaxDynamicSharedMemorySize, score_smem);
    cudaFuncSetAttribute(main_kernel,  cudaFuncAttributeMaxDynamicSharedMemorySize, main_smem);

    score_kernel<<<dim3(30, 64), 256, score_smem>>>(x, Wq, bq, Wk, bk);
    softmax_kernel<<<192, 128>>>(A);
    main_kernel<<<dim3(25, 64), 256, main_smem>>>(x, W, b, y);
}

// round 10
// speedup vs baseline: 1.1635x; 1.0146x over previous
#include <cuda_runtime.h>
#include <cuda_bf16.h>
#include <math.h>

// Shapes (fixed): N=64, T=300, V=25, C=64, K=3, F=64, I=16, d=T*I=4800
#define SCALE_D 0.014433756729740645f   // 1/sqrt(4800)

// Scratch (module-static device memory; no runtime allocation)
__device__ float g_Spart[30 * 3 * 64 * 625];   // [chunk][k][n][v*25+w] partial scores
__device__ float g_Aad[3 * 64 * 625];          // A_adapt [k][n][v*25+w]

// ---------------------------------------------------------------------------
// Kernel 1: attention score partials. EXACT copy of the R5/R9 version (233 us).
// ---------------------------------------------------------------------------
__global__ __launch_bounds__(256) void score_kernel(
    const float* __restrict__ x,
    const float* __restrict__ Wq, const float* __restrict__ bq,
    const float* __restrict__ Wk, const float* __restrict__ bk)
{
    extern __shared__ float sm[];
    float* Gs = sm;            // [64][96] combined Wq|Wk (j<48 Q, j>=48 K)
    float* bs = Gs + 6144;     // [96]
    float* Xs = bs + 96;       // [2][25][68] padded = 3400
    float* Qt = Xs + 3400;     // [2][3][16][28] = 2688 (i-major, v contiguous)
    float* Kt = Qt + 2688;     // [2][3][16][28] = 2688
    // total 15016 floats = 60064 B

    const int tid = threadIdx.x;
    const int chunk = blockIdx.x;
    const int n = blockIdx.y;

    for (int e = tid; e < 6144; e += 256) {
        int c = e / 96, j = e % 96;
        float v;
        if (j < 48)  v = Wq[(j >> 4) * 1024 + c * 16 + (j & 15)];
        else { int jj = j - 48; v = Wk[(jj >> 4) * 1024 + c * 16 + (jj & 15)]; }
        Gs[e] = v;
    }
    if (tid < 96) bs[tid] = (tid < 48) ? bq[tid] : bk[tid - 48];

    const int kq_s = tid / 49;
    const int rs   = tid % 49;
    const int w4_s = rs / 7;
    const int vp_s = rs % 7;
    const bool score_active = (tid < 147);

    float acc[4][4];
#pragma unroll
    for (int a = 0; a < 4; a++)
#pragma unroll
        for (int b2 = 0; b2 < 4; b2++) acc[a][b2] = 0.f;

    const float* xn = x + (n * 300 + chunk * 10) * 1600;

    const int t2   = tid / 120;
    const int re   = tid % 120;
    const int qk   = re / 60;
    const int r2   = re % 60;
    const int rowg = r2 / 12;
    const int ic   = r2 % 12;
    const int kq_e = ic >> 2;
    const int i4   = ic & 3;
    const int gcol = qk * 12 + kq_e * 4 + i4;

    for (int step = 0; step < 5; ++step) {
        __syncthreads();
        {
            const float4* src = (const float4*)(xn + step * 3200);
            float4* dst = (float4*)Xs;
            for (int e = tid; e < 800; e += 256) {
                int tile = e / 400, er = e % 400;
                int row = er >> 4, col = er & 15;
                dst[tile * 425 + row * 17 + col] = src[e];
            }
        }
        __syncthreads();

        if (tid < 240) {
            float a0[5], a1[5], a2[5], a3[5];
#pragma unroll
            for (int rr = 0; rr < 5; rr++) { a0[rr] = a1[rr] = a2[rr] = a3[rr] = 0.f; }

            const float* Xb = Xs + t2 * 1700 + rowg * 340;
            const float4* G4 = (const float4*)Gs;
#pragma unroll 4
            for (int c4 = 0; c4 < 16; ++c4) {
                float4 xr[5];
#pragma unroll
                for (int rr = 0; rr < 5; ++rr)
                    xr[rr] = *(const float4*)(Xb + rr * 68 + c4 * 4);
#pragma unroll
                for (int j = 0; j < 4; ++j) {
                    float4 g = G4[(c4 * 4 + j) * 24 + gcol];
#pragma unroll
                    for (int rr = 0; rr < 5; ++rr) {
                        float xv = (j == 0) ? xr[rr].x : (j == 1) ? xr[rr].y
                                 : (j == 2) ? xr[rr].z : xr[rr].w;
                        a0[rr] += xv * g.x; a1[rr] += xv * g.y;
                        a2[rr] += xv * g.z; a3[rr] += xv * g.w;
                    }
                }
            }
            const int bb0 = qk * 48 + kq_e * 16 + i4 * 4;
            const float b0 = bs[bb0], b1 = bs[bb0 + 1], b2 = bs[bb0 + 2], b3 = bs[bb0 + 3];
            float* eb = (qk ? Kt : Qt) + t2 * 1344 + kq_e * 448 + (i4 * 4) * 28;
#pragma unroll
            for (int rr = 0; rr < 5; ++rr) {
                int row = rowg * 5 + rr;
                eb[row]      = a0[rr] + b0;
                eb[28 + row] = a1[rr] + b1;
                eb[56 + row] = a2[rr] + b2;
                eb[84 + row] = a3[rr] + b3;
            }
        }
        __syncthreads();

        if (score_active) {
#pragma unroll
            for (int ti = 0; ti < 2; ++ti) {
                const float4* qv = (const float4*)(Qt + ti * 1344 + kq_s * 448 + vp_s * 4);
                const float4* kt = (const float4*)(Kt + ti * 1344 + kq_s * 448 + w4_s * 4);
#pragma unroll
                for (int i = 0; i < 16; ++i) {
                    float4 q  = qv[i * 7];
                    float4 kv = kt[i * 7];
                    acc[0][0] += q.x * kv.x; acc[0][1] += q.x * kv.y;
                    acc[0][2] += q.x * kv.z; acc[0][3] += q.x * kv.w;
                    acc[1][0] += q.y * kv.x; acc[1][1] += q.y * kv.y;
                    acc[1][2] += q.y * kv.z; acc[1][3] += q.y * kv.w;
                    acc[2][0] += q.z * kv.x; acc[2][1] += q.z * kv.y;
                    acc[2][2] += q.z * kv.z; acc[2][3] += q.z * kv.w;
                    acc[3][0] += q.w * kv.x; acc[3][1] += q.w * kv.y;
                    acc[3][2] += q.w * kv.z; acc[3][3] += q.w * kv.w;
                }
            }
        }
    }

    if (score_active) {
        float* base = g_Spart + ((chunk * 3 + kq_s) * 64 + n) * 625;
#pragma unroll
        for (int vi = 0; vi < 4; ++vi) {
            int v = vp_s * 4 + vi;
            if (v < 25) {
#pragma unroll
                for (int j = 0; j < 4; ++j) {
                    int w = w4_s * 4 + j;
                    if (w < 25) base[v * 25 + w] = acc[vi][j];
                }
            }
        }
    }
}

// ---------------------------------------------------------------------------
// Kernel 2: reduce chunk partials (deterministic order), softmax, add A.
// ---------------------------------------------------------------------------
__global__ __launch_bounds__(128) void softmax_kernel(const float* __restrict__ A)
{
    __shared__ float S[625];
    const int b = blockIdx.x;
    const int kq = b / 64, n = b % 64;
    const int tid = threadIdx.x;

    for (int e = tid; e < 625; e += 128) {
        float s = 0.f;
        int base = ((kq * 64) + n) * 625 + e;
#pragma unroll 6
        for (int ch = 0; ch < 30; ++ch) s += g_Spart[ch * 120000 + base];
        S[e] = s;
    }
    __syncthreads();

    if (tid < 25) {
        const int v = tid;
        float m = -1e30f;
#pragma unroll
        for (int w = 0; w < 25; ++w) {
            float z = S[v * 25 + w] * SCALE_D;
            m = fmaxf(m, z);
        }
        float p[25];
        float sum = 0.f;
#pragma unroll
        for (int w = 0; w < 25; ++w) {
            p[w] = expf(S[v * 25 + w] * SCALE_D - m);
            sum += p[w];
        }
        float inv = 1.f / sum;
        float* dst = g_Aad + ((kq * 64) + n) * 625 + v * 25;
        const float* Ab = A + kq * 625 + v * 25;
#pragma unroll
        for (int w = 0; w < 25; ++w) dst[w] = Ab[w] + p[w] * inv;
    }
}

// ---------------------------------------------------------------------------
// Kernel 3: main path, tensor-core H.
// H = X*W via mma.sync.m16n8k16 bf16 with 3-term split (hi*hi + hi*lo + lo*hi).
// Y = A^T H scalar float4 (R4 known-good form). Grid (25, 64), 256 threads.
// ---------------------------------------------------------------------------
__device__ __forceinline__ void ldsm_x4(unsigned& r0, unsigned& r1, unsigned& r2, unsigned& r3, unsigned addr) {
    asm volatile("ldmatrix.sync.aligned.m8n8.x4.shared.b16 {%0,%1,%2,%3}, [%4];"
                 : "=r"(r0), "=r"(r1), "=r"(r2), "=r"(r3) : "r"(addr));
}
__device__ __forceinline__ void ldsm_x2t(unsigned& r0, unsigned& r1, unsigned addr) {
    asm volatile("ldmatrix.sync.aligned.m8n8.x2.trans.shared.b16 {%0,%1}, [%2];"
                 : "=r"(r0), "=r"(r1) : "r"(addr));
}
__device__ __forceinline__ void mma_bf16(float* c, const unsigned* a, unsigned b0, unsigned b1) {
    asm volatile("mma.sync.aligned.m16n8k16.row.col.f32.bf16.bf16.f32 "
                 "{%0,%1,%2,%3}, {%4,%5,%6,%7}, {%8,%9}, {%0,%1,%2,%3};"
                 : "+f"(c[0]), "+f"(c[1]), "+f"(c[2]), "+f"(c[3])
                 : "r"(a[0]), "r"(a[1]), "r"(a[2]), "r"(a[3]), "r"(b0), "r"(b1));
}

__global__ __launch_bounds__(256) void main_kernel(
    const float* __restrict__ x, const float* __restrict__ W,
    const float* __restrict__ b, float* __restrict__ y)
{
    extern __shared__ char smraw[];
    __nv_bfloat16* Whi = (__nv_bfloat16*)smraw;        // [64][200] padded
    __nv_bfloat16* Wlo = Whi + 64 * 200;               // [64][200]
    __nv_bfloat16* Xhi = Wlo + 64 * 200;               // [32][72] padded
    __nv_bfloat16* Xlo = Xhi + 32 * 72;                // [32][72]
    float* Hs   = (float*)(Xlo + 32 * 72);             // [32][196] padded
    float* As   = Hs + 32 * 196;                       // [3][25][28] padded = 2100
    float* ybias= As + 2100;                           // [25][64] = 1600
    float* csum = ybias + 1600;                        // [3][25]+pad = 80
    // total = 60416 B + 10052*4 B = 100624 B

    const int tid = threadIdx.x;
    const int lane = tid & 31;
    const int wid = tid >> 5;
    const int n = blockIdx.y;
    const int tc = blockIdx.x;

    // --- W -> bf16 hi/lo (once per block) ---
    for (int e = tid; e < 12288; e += 256) {
        float wv = W[e];
        __nv_bfloat16 hi = __float2bfloat16_rn(wv);
        __nv_bfloat16 lo = __float2bfloat16_rn(wv - __bfloat162float(hi));
        int c = e / 192, f = e % 192;
        Whi[c * 200 + f] = hi;
        Wlo[c * 200 + f] = lo;
    }
    // zero X pad rows 25..31 (both arrays) once
    for (int e = tid; e < 504; e += 256) {
        int r = 25 + e / 72, c = e % 72;
        Xhi[r * 72 + c] = __float2bfloat16_rn(0.f);
        Xlo[r * 72 + c] = __float2bfloat16_rn(0.f);
    }
    // A_adapt repack (stride 28) + pad
    for (int e = tid; e < 1875; e += 256) {
        int k = e / 625, rem = e % 625;
        int v = rem / 25, w = rem % 25;
        As[k * 700 + v * 28 + w] = g_Aad[(k * 64 + n) * 625 + rem];
    }
    for (int e = tid; e < 225; e += 256) {
        int k = e / 75, r = e % 75;
        As[k * 700 + (r / 3) * 28 + 25 + (r % 3)] = 0.f;
    }
    __syncthreads();

    if (tid < 75) {
        int k = tid / 25, w = tid % 25;
        float s = 0.f;
#pragma unroll
        for (int v = 0; v < 25; ++v) s += As[k * 700 + v * 28 + w];
        csum[tid] = s;
    }
    __syncthreads();
    for (int e = tid; e < 1600; e += 256) {
        int w = e / 64, f = e % 64;
        ybias[e] = b[f] * csum[w] + b[64 + f] * csum[25 + w] + b[128 + f] * csum[50 + w];
    }

    // --- mma warp decode ---
    const int mt = wid >> 2;            // 0..1 (m tile of 16)
    const int nb = wid & 3;             // base n tile; tiles nb+4i, i=0..5
    const unsigned xhiB = (unsigned)__cvta_generic_to_shared(Xhi);
    const unsigned xloB = (unsigned)__cvta_generic_to_shared(Xlo);
    const unsigned whiB = (unsigned)__cvta_generic_to_shared(Whi);
    const unsigned wloB = (unsigned)__cvta_generic_to_shared(Wlo);
    const int arow = mt * 16 + ((lane >> 3) & 1) * 8 + (lane & 7);
    const unsigned aoff = (unsigned)(arow * 144 + (lane >> 4) * 16);  // bytes
    const unsigned boff = (unsigned)((lane & 15) * 400);              // bytes

    // --- Y phase decode (112 threads) ---
    const int w4 = tid / 16;            // 0..6
    const int f4 = tid % 16;            // 0..15

    for (int tt = 0; tt < 12; ++tt) {
        const int t = tc * 12 + tt;
        __syncthreads();
        // --- convert X(t) -> bf16 hi/lo ---
        {
            const float* src = x + (n * 300 + t) * 1600;
            for (int e = tid; e < 1600; e += 256) {
                float xv = src[e];
                __nv_bfloat16 hi = __float2bfloat16_rn(xv);
                __nv_bfloat16 lo = __float2bfloat16_rn(xv - __bfloat162float(hi));
                int r = e >> 6, c = e & 63;
                Xhi[r * 72 + c] = hi;
                Xlo[r * 72 + c] = lo;
            }
        }
        __syncthreads();

        // --- H = X*W on tensor cores: each warp 6 m16n8 tiles ---
        {
            float acc[6][4];
#pragma unroll
            for (int i = 0; i < 6; ++i)
#pragma unroll
                for (int j = 0; j < 4; ++j) acc[i][j] = 0.f;

#pragma unroll
            for (int ks = 0; ks < 4; ++ks) {
                unsigned ahi[4], alo[4];
                ldsm_x4(ahi[0], ahi[1], ahi[2], ahi[3], xhiB + aoff + ks * 32);
                ldsm_x4(alo[0], alo[1], alo[2], alo[3], xloB + aoff + ks * 32);
#pragma unroll
                for (int i = 0; i < 6; ++i) {
                    const int n0 = (nb + 4 * i) * 8;
                    unsigned kb = boff + (unsigned)(ks * 6400 + n0 * 2);
                    unsigned bh0, bh1, bl0, bl1;
                    ldsm_x2t(bh0, bh1, whiB + kb);
                    ldsm_x2t(bl0, bl1, wloB + kb);
                    mma_bf16(acc[i], ahi, bh0, bh1);
                    mma_bf16(acc[i], ahi, bl0, bl1);
                    mma_bf16(acc[i], alo, bh0, bh1);
                }
            }
            const int crow = mt * 16 + (lane >> 2);
            const int ccol = 2 * (lane & 3);
#pragma unroll
            for (int i = 0; i < 6; ++i) {
                const int n0 = (nb + 4 * i) * 8;
                *(float2*)&Hs[crow * 196 + n0 + ccol]       = make_float2(acc[i][0], acc[i][1]);
                *(float2*)&Hs[(crow + 8) * 196 + n0 + ccol] = make_float2(acc[i][2], acc[i][3]);
            }
        }
        __syncthreads();

        // --- Y: 4w x 4f tiles, 112 threads, scalar float4 (R4 form) ---
        if (tid < 112) {
            const float4* H4 = (const float4*)Hs;     // row stride 49 float4
            const float4* yb4 = (const float4*)ybias;
            float4 s[4];
#pragma unroll
            for (int j = 0; j < 4; ++j) {
                int w = w4 * 4 + j;
                s[j] = (w < 25) ? yb4[w * 16 + f4] : make_float4(0.f, 0.f, 0.f, 0.f);
            }
#pragma unroll
            for (int k = 0; k < 3; ++k) {
                const float* Ab = As + k * 700 + w4 * 4;
                const int hcol = k * 16 + f4;
#pragma unroll 5
                for (int v = 0; v < 25; ++v) {
                    float4 h = H4[v * 49 + hcol];
                    float4 a = *(const float4*)(Ab + v * 28);
                    s[0].x += a.x * h.x; s[0].y += a.x * h.y; s[0].z += a.x * h.z; s[0].w += a.x * h.w;
                    s[1].x += a.y * h.x; s[1].y += a.y * h.y; s[1].z += a.y * h.z; s[1].w += a.y * h.w;
                    s[2].x += a.z * h.x; s[2].y += a.z * h.y; s[2].z += a.z * h.z; s[2].w += a.z * h.w;
                    s[3].x += a.w * h.x; s[3].y += a.w * h.y; s[3].z += a.w * h.z; s[3].w += a.w * h.w;
                }
            }
            float4* yout = (float4*)(y + (n * 300 + t) * 1600);
#pragma unroll
            for (int j = 0; j < 4; ++j) {
                int w = w4 * 4 + j;
                if (w < 25) yout[w * 16 + f4] = s[j];
            }
        }
    }
}

// ---------------------------------------------------------------------------
extern "C" void kernel_launch(void* const* d_in, const int* in_sizes, int n_in,
                              void* d_out, int out_size)
{
    const float* x  = (const float*)d_in[0];
    const float* A  = (const float*)d_in[1];
    const float* W  = (const float*)d_in[2];
    const float* b  = (const float*)d_in[3];
    const float* Wq = (const float*)d_in[4];
    const float* bq = (const float*)d_in[5];
    const float* Wk = (const float*)d_in[6];
    const float* bk = (const float*)d_in[7];
    float* y = (float*)d_out;

    const int score_smem = 15016 * 4;   // 60064 B
    const int main_smem  = 100624;      // bytes
    cudaFuncSetAttribute(score_kernel, cudaFuncAttributeMaxDynamicSharedMemorySize, score_smem);
    cudaFuncSetAttribute(main_kernel,  cudaFuncAttributeMaxDynamicSharedMemorySize, main_smem);

    score_kernel<<<dim3(30, 64), 256, score_smem>>>(x, Wq, bq, Wk, bk);
    softmax_kernel<<<192, 128>>>(A);
    main_kernel<<<dim3(25, 64), 256, main_smem>>>(x, W, b, y);
}

// round 11
// speedup vs baseline: 1.5142x; 1.3014x over previous
#include <cuda_runtime.h>
#include <cuda_bf16.h>
#include <math.h>

// Shapes (fixed): N=64, T=300, V=25, C=64, K=3, F=64, I=16, d=T*I=4800
#define SCALE_D 0.014433756729740645f   // 1/sqrt(4800)

typedef unsigned long long u64;

__device__ __forceinline__ u64 pk2(float lo, float hi) {
    u64 r; asm("mov.b64 %0, {%1, %2};" : "=l"(r) : "f"(lo), "f"(hi)); return r;
}
__device__ __forceinline__ void up2(u64 v, float& a, float& b) {
    asm("mov.b64 {%0, %1}, %2;" : "=f"(a), "=f"(b) : "l"(v));
}
__device__ __forceinline__ void fma2(u64& d, u64 a, u64 b) {
    asm("fma.rn.f32x2 %0, %1, %2, %0;" : "+l"(d) : "l"(a), "l"(b));
}

// Scratch (module-static device memory; no runtime allocation)
__device__ float g_Spart[30 * 3 * 64 * 625];   // [chunk][k][n][v*25+w] partial scores
__device__ float g_Aad[3 * 64 * 625];          // A_adapt [k][n][v*25+w]

// ---------------------------------------------------------------------------
// Kernel 1: attention score partials. EXACT copy of the R5/R9 version (231 us).
// ---------------------------------------------------------------------------
__global__ __launch_bounds__(256) void score_kernel(
    const float* __restrict__ x,
    const float* __restrict__ Wq, const float* __restrict__ bq,
    const float* __restrict__ Wk, const float* __restrict__ bk)
{
    extern __shared__ float sm[];
    float* Gs = sm;            // [64][96]
    float* bs = Gs + 6144;     // [96]
    float* Xs = bs + 96;       // [2][25][68] = 3400
    float* Qt = Xs + 3400;     // [2][3][16][28] = 2688
    float* Kt = Qt + 2688;     // [2][3][16][28] = 2688

    const int tid = threadIdx.x;
    const int chunk = blockIdx.x;
    const int n = blockIdx.y;

    for (int e = tid; e < 6144; e += 256) {
        int c = e / 96, j = e % 96;
        float v;
        if (j < 48)  v = Wq[(j >> 4) * 1024 + c * 16 + (j & 15)];
        else { int jj = j - 48; v = Wk[(jj >> 4) * 1024 + c * 16 + (jj & 15)]; }
        Gs[e] = v;
    }
    if (tid < 96) bs[tid] = (tid < 48) ? bq[tid] : bk[tid - 48];

    const int kq_s = tid / 49;
    const int rs   = tid % 49;
    const int w4_s = rs / 7;
    const int vp_s = rs % 7;
    const bool score_active = (tid < 147);

    float acc[4][4];
#pragma unroll
    for (int a = 0; a < 4; a++)
#pragma unroll
        for (int b2 = 0; b2 < 4; b2++) acc[a][b2] = 0.f;

    const float* xn = x + (n * 300 + chunk * 10) * 1600;

    const int t2   = tid / 120;
    const int re   = tid % 120;
    const int qk   = re / 60;
    const int r2   = re % 60;
    const int rowg = r2 / 12;
    const int ic   = r2 % 12;
    const int kq_e = ic >> 2;
    const int i4   = ic & 3;
    const int gcol = qk * 12 + kq_e * 4 + i4;

    for (int step = 0; step < 5; ++step) {
        __syncthreads();
        {
            const float4* src = (const float4*)(xn + step * 3200);
            float4* dst = (float4*)Xs;
            for (int e = tid; e < 800; e += 256) {
                int tile = e / 400, er = e % 400;
                int row = er >> 4, col = er & 15;
                dst[tile * 425 + row * 17 + col] = src[e];
            }
        }
        __syncthreads();

        if (tid < 240) {
            float a0[5], a1[5], a2[5], a3[5];
#pragma unroll
            for (int rr = 0; rr < 5; rr++) { a0[rr] = a1[rr] = a2[rr] = a3[rr] = 0.f; }

            const float* Xb = Xs + t2 * 1700 + rowg * 340;
            const float4* G4 = (const float4*)Gs;
#pragma unroll 4
            for (int c4 = 0; c4 < 16; ++c4) {
                float4 xr[5];
#pragma unroll
                for (int rr = 0; rr < 5; ++rr)
                    xr[rr] = *(const float4*)(Xb + rr * 68 + c4 * 4);
#pragma unroll
                for (int j = 0; j < 4; ++j) {
                    float4 g = G4[(c4 * 4 + j) * 24 + gcol];
#pragma unroll
                    for (int rr = 0; rr < 5; ++rr) {
                        float xv = (j == 0) ? xr[rr].x : (j == 1) ? xr[rr].y
                                 : (j == 2) ? xr[rr].z : xr[rr].w;
                        a0[rr] += xv * g.x; a1[rr] += xv * g.y;
                        a2[rr] += xv * g.z; a3[rr] += xv * g.w;
                    }
                }
            }
            const int bb0 = qk * 48 + kq_e * 16 + i4 * 4;
            const float b0 = bs[bb0], b1 = bs[bb0 + 1], b2 = bs[bb0 + 2], b3 = bs[bb0 + 3];
            float* eb = (qk ? Kt : Qt) + t2 * 1344 + kq_e * 448 + (i4 * 4) * 28;
#pragma unroll
            for (int rr = 0; rr < 5; ++rr) {
                int row = rowg * 5 + rr;
                eb[row]      = a0[rr] + b0;
                eb[28 + row] = a1[rr] + b1;
                eb[56 + row] = a2[rr] + b2;
                eb[84 + row] = a3[rr] + b3;
            }
        }
        __syncthreads();

        if (score_active) {
#pragma unroll
            for (int ti = 0; ti < 2; ++ti) {
                const float4* qv = (const float4*)(Qt + ti * 1344 + kq_s * 448 + vp_s * 4);
                const float4* kt = (const float4*)(Kt + ti * 1344 + kq_s * 448 + w4_s * 4);
#pragma unroll
                for (int i = 0; i < 16; ++i) {
                    float4 q  = qv[i * 7];
                    float4 kv = kt[i * 7];
                    acc[0][0] += q.x * kv.x; acc[0][1] += q.x * kv.y;
                    acc[0][2] += q.x * kv.z; acc[0][3] += q.x * kv.w;
                    acc[1][0] += q.y * kv.x; acc[1][1] += q.y * kv.y;
                    acc[1][2] += q.y * kv.z; acc[1][3] += q.y * kv.w;
                    acc[2][0] += q.z * kv.x; acc[2][1] += q.z * kv.y;
                    acc[2][2] += q.z * kv.z; acc[2][3] += q.z * kv.w;
                    acc[3][0] += q.w * kv.x; acc[3][1] += q.w * kv.y;
                    acc[3][2] += q.w * kv.z; acc[3][3] += q.w * kv.w;
                }
            }
        }
    }

    if (score_active) {
        float* base = g_Spart + ((chunk * 3 + kq_s) * 64 + n) * 625;
#pragma unroll
        for (int vi = 0; vi < 4; ++vi) {
            int v = vp_s * 4 + vi;
            if (v < 25) {
#pragma unroll
                for (int j = 0; j < 4; ++j) {
                    int w = w4_s * 4 + j;
                    if (w < 25) base[v * 25 + w] = acc[vi][j];
                }
            }
        }
    }
}

// ---------------------------------------------------------------------------
// Kernel 2: reduce chunk partials, softmax, add A.
// ---------------------------------------------------------------------------
__global__ __launch_bounds__(128) void softmax_kernel(const float* __restrict__ A)
{
    __shared__ float S[625];
    const int b = blockIdx.x;
    const int kq = b / 64, n = b % 64;
    const int tid = threadIdx.x;

    for (int e = tid; e < 625; e += 128) {
        float s = 0.f;
        int base = ((kq * 64) + n) * 625 + e;
#pragma unroll 6
        for (int ch = 0; ch < 30; ++ch) s += g_Spart[ch * 120000 + base];
        S[e] = s;
    }
    __syncthreads();

    if (tid < 25) {
        const int v = tid;
        float m = -1e30f;
#pragma unroll
        for (int w = 0; w < 25; ++w) {
            float z = S[v * 25 + w] * SCALE_D;
            m = fmaxf(m, z);
        }
        float p[25];
        float sum = 0.f;
#pragma unroll
        for (int w = 0; w < 25; ++w) {
            p[w] = expf(S[v * 25 + w] * SCALE_D - m);
            sum += p[w];
        }
        float inv = 1.f / sum;
        float* dst = g_Aad + ((kq * 64) + n) * 625 + v * 25;
        const float* Ab = A + kq * 625 + v * 25;
#pragma unroll
        for (int w = 0; w < 25; ++w) dst[w] = Ab[w] + p[w] * inv;
    }
}

// ---------------------------------------------------------------------------
// Kernel 3: main path, pipelined. Grid (25, 64), 256 threads.
// H = X*W tensor-core (bf16 3-term split, x4/x4t ldsm).
// Y = A^T H on 7 warps (v-split + combine, FFMA2) while warp 7 converts X(t+1).
// ---------------------------------------------------------------------------
__device__ __forceinline__ void ldsm_x4(unsigned& r0, unsigned& r1, unsigned& r2, unsigned& r3, unsigned addr) {
    asm volatile("ldmatrix.sync.aligned.m8n8.x4.shared.b16 {%0,%1,%2,%3}, [%4];"
                 : "=r"(r0), "=r"(r1), "=r"(r2), "=r"(r3) : "r"(addr));
}
__device__ __forceinline__ void ldsm_x4t(unsigned& r0, unsigned& r1, unsigned& r2, unsigned& r3, unsigned addr) {
    asm volatile("ldmatrix.sync.aligned.m8n8.x4.trans.shared.b16 {%0,%1,%2,%3}, [%4];"
                 : "=r"(r0), "=r"(r1), "=r"(r2), "=r"(r3) : "r"(addr));
}
__device__ __forceinline__ void mma_bf16(float* c, const unsigned* a, unsigned b0, unsigned b1) {
    asm volatile("mma.sync.aligned.m16n8k16.row.col.f32.bf16.bf16.f32 "
                 "{%0,%1,%2,%3}, {%4,%5,%6,%7}, {%8,%9}, {%0,%1,%2,%3};"
                 : "+f"(c[0]), "+f"(c[1]), "+f"(c[2]), "+f"(c[3])
                 : "r"(a[0]), "r"(a[1]), "r"(a[2]), "r"(a[3]), "r"(b0), "r"(b1));
}

// smem byte offsets
#define SM_WHI   0            // bf16 [64][200]  25600 B
#define SM_WLO   25600        // bf16 [64][200]  25600 B
#define SM_XBUF  51200        // 2 bufs x (Xhi[32][72] + Xlo[32][72]) = 2 x 9216 B
#define SM_HS    69632        // f32 [25][196]   19600 B
#define SM_AS    89232        // f32 [3][25][28]  8400 B
#define SM_STG   97632        // f32 [112][16]    7168 B
#define SM_CSUM  104800       // f32 [80]          320 B
#define SM_BSM   105120       // f32 [192]         768 B
#define SM_TOTAL 105888

__global__ __launch_bounds__(256) void main_kernel(
    const float* __restrict__ x, const float* __restrict__ W,
    const float* __restrict__ b, float* __restrict__ y)
{
    extern __shared__ char smraw[];
    __nv_bfloat16* Whi = (__nv_bfloat16*)(smraw + SM_WHI);
    __nv_bfloat16* Wlo = (__nv_bfloat16*)(smraw + SM_WLO);
    float* Hs   = (float*)(smraw + SM_HS);
    float* As   = (float*)(smraw + SM_AS);
    float* stg  = (float*)(smraw + SM_STG);
    float* csum = (float*)(smraw + SM_CSUM);
    float* bsm  = (float*)(smraw + SM_BSM);

    const int tid = threadIdx.x;
    const int lane = tid & 31;
    const int wid = tid >> 5;
    const int n = blockIdx.y;
    const int tc = blockIdx.x;

    // --- init: W -> bf16 hi/lo ---
    for (int e = tid; e < 12288; e += 256) {
        float wv = W[e];
        __nv_bfloat16 hi = __float2bfloat16_rn(wv);
        __nv_bfloat16 lo = __float2bfloat16_rn(wv - __bfloat162float(hi));
        int c = e / 192, f = e % 192;
        Whi[c * 200 + f] = hi;
        Wlo[c * 200 + f] = lo;
    }
    // zero X pad rows 25..31 in both buffers (hi+lo)
    for (int e = tid; e < 1008; e += 256) {             // 2 bufs * 7 rows * 72
        int buf = e / 504, r = 25 + (e % 504) / 72, c = e % 72;
        __nv_bfloat16* Xh = (__nv_bfloat16*)(smraw + SM_XBUF + buf * 9216);
        __nv_bfloat16* Xl = Xh + 2304;
        Xh[r * 72 + c] = __float2bfloat16_rn(0.f);
        Xl[r * 72 + c] = __float2bfloat16_rn(0.f);
    }
    // A_adapt repack (stride 28) + pad
    for (int e = tid; e < 1875; e += 256) {
        int k = e / 625, rem = e % 625;
        int v = rem / 25, w = rem % 25;
        As[k * 700 + v * 28 + w] = g_Aad[(k * 64 + n) * 625 + rem];
    }
    for (int e = tid; e < 225; e += 256) {
        int k = e / 75, r = e % 75;
        As[k * 700 + (r / 3) * 28 + 25 + (r % 3)] = 0.f;
    }
    if (tid < 192) bsm[tid] = b[tid];
    __syncthreads();

    if (tid < 75) {
        int k = tid / 25, w = tid % 25;
        float s = 0.f;
#pragma unroll
        for (int v = 0; v < 25; ++v) s += As[k * 700 + v * 28 + w];
        csum[tid] = s;
    }
    __syncthreads();

    // --- Y decode + register bias ---
    const int vh    = (tid < 224) ? tid / 112 : 0;
    const int ytile = (tid < 224) ? tid % 112 : 0;
    const int w4 = ytile / 16;
    const int f4 = ytile % 16;
    u64 yb[4][2];
    if (tid < 224) {
#pragma unroll
        for (int j = 0; j < 4; ++j) {
            int w = w4 * 4 + j;
            if (vh == 0 && w < 25) {
#pragma unroll
                for (int p = 0; p < 2; ++p) {
                    int f0 = f4 * 4 + 2 * p;
                    float v0 = bsm[f0]     * csum[w] + bsm[64 + f0]     * csum[25 + w]
                             + bsm[128 + f0]     * csum[50 + w];
                    float v1 = bsm[f0 + 1] * csum[w] + bsm[64 + f0 + 1] * csum[25 + w]
                             + bsm[128 + f0 + 1] * csum[50 + w];
                    yb[j][p] = pk2(v0, v1);
                }
            } else { yb[j][0] = 0ull; yb[j][1] = 0ull; }
        }
    }

    // --- prologue: convert X(t0) into buffer 0 (all threads) ---
    {
        const float4* src = (const float4*)(x + (n * 300 + tc * 12) * 1600);
        __nv_bfloat16* Xh = (__nv_bfloat16*)(smraw + SM_XBUF);
        __nv_bfloat16* Xl = Xh + 2304;
        for (int e = tid; e < 400; e += 256) {
            float4 v = src[e];
            int r = e >> 4, c = (e & 15) * 4;
            __nv_bfloat16 h0 = __float2bfloat16_rn(v.x), h1 = __float2bfloat16_rn(v.y);
            __nv_bfloat16 h2 = __float2bfloat16_rn(v.z), h3 = __float2bfloat16_rn(v.w);
            Xh[r * 72 + c]     = h0; Xh[r * 72 + c + 1] = h1;
            Xh[r * 72 + c + 2] = h2; Xh[r * 72 + c + 3] = h3;
            Xl[r * 72 + c]     = __float2bfloat16_rn(v.x - __bfloat162float(h0));
            Xl[r * 72 + c + 1] = __float2bfloat16_rn(v.y - __bfloat162float(h1));
            Xl[r * 72 + c + 2] = __float2bfloat16_rn(v.z - __bfloat162float(h2));
            Xl[r * 72 + c + 3] = __float2bfloat16_rn(v.w - __bfloat162float(h3));
        }
    }
    __syncthreads();

    // --- mma decode ---
    const int mt = wid >> 2;            // m tile 0..1
    const int nb = wid & 3;             // chunk base; chunks nb, nb+4, nb+8 (16 cols each)
    const int arow = mt * 16 + ((lane >> 3) & 1) * 8 + (lane & 7);
    const unsigned aoff = (unsigned)(arow * 144 + (lane >> 4) * 16);
    const unsigned boff = (unsigned)((lane & 15) * 400 + (lane >> 4) * 16);
    const unsigned whiB = (unsigned)__cvta_generic_to_shared(Whi);
    const unsigned wloB = (unsigned)__cvta_generic_to_shared(Wlo);
    const unsigned xbufB = (unsigned)__cvta_generic_to_shared(smraw + SM_XBUF);

    for (int it = 0; it < 12; ++it) {
        const int t = tc * 12 + it;
        const unsigned xhiB = xbufB + (unsigned)((it & 1) * 9216);
        const unsigned xloB = xhiB + 4608;

        // --- H = X*W tensor cores (all 8 warps) ---
        {
            float acc[6][4];
#pragma unroll
            for (int i = 0; i < 6; ++i)
#pragma unroll
                for (int j = 0; j < 4; ++j) acc[i][j] = 0.f;

#pragma unroll
            for (int ks = 0; ks < 4; ++ks) {
                unsigned ahi[4], alo[4];
                ldsm_x4(ahi[0], ahi[1], ahi[2], ahi[3], xhiB + aoff + ks * 32);
                ldsm_x4(alo[0], alo[1], alo[2], alo[3], xloB + aoff + ks * 32);
#pragma unroll
                for (int c3 = 0; c3 < 3; ++c3) {
                    const int chunk = nb + 4 * c3;
                    const unsigned kb = boff + (unsigned)(ks * 6400 + chunk * 32);
                    unsigned bh[4], bl[4];
                    ldsm_x4t(bh[0], bh[1], bh[2], bh[3], whiB + kb);
                    ldsm_x4t(bl[0], bl[1], bl[2], bl[3], wloB + kb);
                    float* a0 = acc[c3 * 2];
                    float* a1 = acc[c3 * 2 + 1];
                    mma_bf16(a0, ahi, bh[0], bh[1]);
                    mma_bf16(a0, ahi, bl[0], bl[1]);
                    mma_bf16(a0, alo, bh[0], bh[1]);
                    mma_bf16(a1, ahi, bh[2], bh[3]);
                    mma_bf16(a1, ahi, bl[2], bl[3]);
                    mma_bf16(a1, alo, bh[2], bh[3]);
                }
            }
            const int crow = mt * 16 + (lane >> 2);
            const int ccol = 2 * (lane & 3);
            const bool s0ok = (crow < 25);
            const bool s1ok = (crow + 8 < 25);
#pragma unroll
            for (int c3 = 0; c3 < 3; ++c3) {
#pragma unroll
                for (int nt = 0; nt < 2; ++nt) {
                    const int n0 = (nb + 4 * c3) * 16 + nt * 8;
                    const float* a = acc[c3 * 2 + nt];
                    if (s0ok) *(float2*)&Hs[crow * 196 + n0 + ccol]       = make_float2(a[0], a[1]);
                    if (s1ok) *(float2*)&Hs[(crow + 8) * 196 + n0 + ccol] = make_float2(a[2], a[3]);
                }
            }
        }
        __syncthreads();

        // --- Y (warps 0-6, v-split)  ||  convert X(t+1) (warp 7) ---
        u64 s2[4][2];
        if (tid < 224) {
#pragma unroll
            for (int j = 0; j < 4; ++j) { s2[j][0] = yb[j][0]; s2[j][1] = yb[j][1]; }
            const int vbeg = vh ? 13 : 0;
            const int vend = vh ? 25 : 13;
            const ulonglong2* H2 = (const ulonglong2*)Hs;    // row = 49 ull2
#pragma unroll
            for (int k = 0; k < 3; ++k) {
                const float* Ab = As + k * 700 + w4 * 4;
                const int hidx = k * 16 + f4;
                for (int v = vbeg; v < vend; ++v) {
                    float4 a = *(const float4*)(Ab + v * 28);
                    ulonglong2 h = H2[v * 49 + hidx];
                    u64 d0 = pk2(a.x, a.x), d1 = pk2(a.y, a.y);
                    u64 d2 = pk2(a.z, a.z), d3 = pk2(a.w, a.w);
                    fma2(s2[0][0], d0, h.x); fma2(s2[0][1], d0, h.y);
                    fma2(s2[1][0], d1, h.x); fma2(s2[1][1], d1, h.y);
                    fma2(s2[2][0], d2, h.x); fma2(s2[2][1], d2, h.y);
                    fma2(s2[3][0], d3, h.x); fma2(s2[3][1], d3, h.y);
                }
            }
            if (vh == 1) {
                u64* st = (u64*)stg;
#pragma unroll
                for (int j = 0; j < 4; ++j) {
                    st[ytile * 8 + j * 2]     = s2[j][0];
                    st[ytile * 8 + j * 2 + 1] = s2[j][1];
                }
            }
        } else if (wid == 7 && it < 11) {
            // convert X(t+1) into the other buffer
            const float4* src = (const float4*)(x + (n * 300 + t + 1) * 1600);
            __nv_bfloat16* Xh = (__nv_bfloat16*)(smraw + SM_XBUF + ((it + 1) & 1) * 9216);
            __nv_bfloat16* Xl = Xh + 2304;
            for (int e = lane; e < 400; e += 32) {
                float4 v = src[e];
                int r = e >> 4, c = (e & 15) * 4;
                __nv_bfloat16 h0 = __float2bfloat16_rn(v.x), h1 = __float2bfloat16_rn(v.y);
                __nv_bfloat16 h2 = __float2bfloat16_rn(v.z), h3 = __float2bfloat16_rn(v.w);
                Xh[r * 72 + c]     = h0; Xh[r * 72 + c + 1] = h1;
                Xh[r * 72 + c + 2] = h2; Xh[r * 72 + c + 3] = h3;
                Xl[r * 72 + c]     = __float2bfloat16_rn(v.x - __bfloat162float(h0));
                Xl[r * 72 + c + 1] = __float2bfloat16_rn(v.y - __bfloat162float(h1));
                Xl[r * 72 + c + 2] = __float2bfloat16_rn(v.z - __bfloat162float(h2));
                Xl[r * 72 + c + 3] = __float2bfloat16_rn(v.w - __bfloat162float(h3));
            }
        }
        __syncthreads();

        // --- combine halves + store y (vh0 threads) ---
        if (tid < 112) {
            const u64* st = (const u64*)stg;
            float4* yout = (float4*)(y + (n * 300 + t) * 1600);
#pragma unroll
            for (int j = 0; j < 4; ++j) {
                int w = w4 * 4 + j;
                if (w < 25) {
                    float p0, p1, p2, p3, o0, o1, o2, o3;
                    up2(s2[j][0], p0, p1);
                    up2(s2[j][1], p2, p3);
                    up2(st[ytile * 8 + j * 2],     o0, o1);
                    up2(st[ytile * 8 + j * 2 + 1], o2, o3);
                    yout[w * 16 + f4] = make_float4(p0 + o0, p1 + o1, p2 + o2, p3 + o3);
                }
            }
        }
    }
}

// ---------------------------------------------------------------------------
extern "C" void kernel_launch(void* const* d_in, const int* in_sizes, int n_in,
                              void* d_out, int out_size)
{
    const float* x  = (const float*)d_in[0];
    const float* A  = (const float*)d_in[1];
    const float* W  = (const float*)d_in[2];
    const float* b  = (const float*)d_in[3];
    const float* Wq = (const float*)d_in[4];
    const float* bq = (const float*)d_in[5];
    const float* Wk = (const float*)d_in[6];
    const float* bk = (const float*)d_in[7];
    float* y = (float*)d_out;

    const int score_smem = 15016 * 4;   // 60064 B
    cudaFuncSetAttribute(score_kernel, cudaFuncAttributeMaxDynamicSharedMemorySize, score_smem);
    cudaFuncSetAttribute(main_kernel,  cudaFuncAttributeMaxDynamicSharedMemorySize, SM_TOTAL);

    score_kernel<<<dim3(30, 64), 256, score_smem>>>(x, Wq, bq, Wk, bk);
    softmax_kernel<<<192, 128>>>(A);
    main_kernel<<<dim3(25, 64), 256, SM_TOTAL>>>(x, W, b, y);
}

// round 12
// speedup vs baseline: 1.6425x; 1.0848x over previous
#include <cuda_runtime.h>
#include <cuda_bf16.h>
#include <math.h>

// Shapes (fixed): N=64, T=300, V=25, C=64, K=3, F=64, I=16, d=T*I=4800
#define SCALE_D 0.014433756729740645f   // 1/sqrt(4800)

typedef unsigned long long u64;

__device__ __forceinline__ u64 pk2(float lo, float hi) {
    u64 r; asm("mov.b64 %0, {%1, %2};" : "=l"(r) : "f"(lo), "f"(hi)); return r;
}
__device__ __forceinline__ void up2(u64 v, float& a, float& b) {
    asm("mov.b64 {%0, %1}, %2;" : "=f"(a), "=f"(b) : "l"(v));
}
__device__ __forceinline__ void fma2(u64& d, u64 a, u64 b) {
    asm("fma.rn.f32x2 %0, %1, %2, %0;" : "+l"(d) : "l"(a), "l"(b));
}

__device__ __forceinline__ void ldsm_x4(unsigned& r0, unsigned& r1, unsigned& r2, unsigned& r3, unsigned addr) {
    asm volatile("ldmatrix.sync.aligned.m8n8.x4.shared.b16 {%0,%1,%2,%3}, [%4];"
                 : "=r"(r0), "=r"(r1), "=r"(r2), "=r"(r3) : "r"(addr));
}
__device__ __forceinline__ void ldsm_x4t(unsigned& r0, unsigned& r1, unsigned& r2, unsigned& r3, unsigned addr) {
    asm volatile("ldmatrix.sync.aligned.m8n8.x4.trans.shared.b16 {%0,%1,%2,%3}, [%4];"
                 : "=r"(r0), "=r"(r1), "=r"(r2), "=r"(r3) : "r"(addr));
}
__device__ __forceinline__ void mma_bf16(float* c, const unsigned* a, unsigned b0, unsigned b1) {
    asm volatile("mma.sync.aligned.m16n8k16.row.col.f32.bf16.bf16.f32 "
                 "{%0,%1,%2,%3}, {%4,%5,%6,%7}, {%8,%9}, {%0,%1,%2,%3};"
                 : "+f"(c[0]), "+f"(c[1]), "+f"(c[2]), "+f"(c[3])
                 : "r"(a[0]), "r"(a[1]), "r"(a[2]), "r"(a[3]), "r"(b0), "r"(b1));
}

// Scratch (module-static device memory; no runtime allocation)
__device__ float g_Spart[30 * 3 * 64 * 625];   // [chunk][k][n][v*25+w] partial scores
__device__ float g_Aad[3 * 64 * 625];          // A_adapt [k][n][v*25+w]

// ---------------------------------------------------------------------------
// Kernel 1: attention score partials, tensor-core embedding.
// Grid (30, 64), 256 threads. Per step: convert 2 t-tiles of X to bf16 hi/lo
// (rows 0-49 of a 64-row A), E = X*[Wq|Wk] on mma (bf16 3-term split), bias
// added fp32 at fragment store, transposed into Qt/Kt (i-major, stride 28).
// Score accumulation phase: unchanged scalar float4 form.
// ---------------------------------------------------------------------------
// smem byte offsets (score kernel)
#define SC_GHI   0            // bf16 [64][104]  13312 B
#define SC_GLO   13312        // bf16 [64][104]  13312 B
#define SC_XH    26624        // bf16 [64][72]    9216 B
#define SC_XL    35840        // bf16 [64][72]    9216 B
#define SC_QT    45056        // f32 [2][3][16][28] 10752 B
#define SC_KT    55808        // f32 [2][3][16][28] 10752 B
#define SC_BS    66560        // f32 [96]           384 B
#define SC_TOTAL 66944

__global__ __launch_bounds__(256) void score_kernel(
    const float* __restrict__ x,
    const float* __restrict__ Wq, const float* __restrict__ bq,
    const float* __restrict__ Wk, const float* __restrict__ bk)
{
    extern __shared__ char smraw[];
    __nv_bfloat16* Ghi = (__nv_bfloat16*)(smraw + SC_GHI);
    __nv_bfloat16* Glo = (__nv_bfloat16*)(smraw + SC_GLO);
    __nv_bfloat16* Xh  = (__nv_bfloat16*)(smraw + SC_XH);
    __nv_bfloat16* Xl  = (__nv_bfloat16*)(smraw + SC_XL);
    float* Qt = (float*)(smraw + SC_QT);
    float* Kt = (float*)(smraw + SC_KT);
    float* bs = (float*)(smraw + SC_BS);

    const int tid = threadIdx.x;
    const int lane = tid & 31;
    const int wid = tid >> 5;
    const int chunk = blockIdx.x;
    const int n = blockIdx.y;

    // --- G = [Wq|Wk] -> bf16 hi/lo, row-major [c=64][j=96], stride 104 ---
    for (int e = tid; e < 6144; e += 256) {
        int c = e / 96, j = e % 96;
        float v;
        if (j < 48)  v = Wq[(j >> 4) * 1024 + c * 16 + (j & 15)];
        else { int jj = j - 48; v = Wk[(jj >> 4) * 1024 + c * 16 + (jj & 15)]; }
        __nv_bfloat16 hi = __float2bfloat16_rn(v);
        Ghi[c * 104 + j] = hi;
        Glo[c * 104 + j] = __float2bfloat16_rn(v - __bfloat162float(hi));
    }
    if (tid < 96) bs[tid] = (tid < 48) ? bq[tid] : bk[tid - 48];
    // zero X pad rows 50..63 (hi+lo)
    for (int e = tid; e < 1008; e += 256) {
        int r = 50 + e / 72, c = e % 72;
        Xh[r * 72 + c] = __float2bfloat16_rn(0.f);
        Xl[r * 72 + c] = __float2bfloat16_rn(0.f);
    }

    // Score-phase task decode: 147 tasks = 3 kq x 7 w4 x 7 vp (4v x 4w tiles)
    const int kq_s = tid / 49;
    const int rs   = tid % 49;
    const int w4_s = rs / 7;
    const int vp_s = rs % 7;
    const bool score_active = (tid < 147);

    float acc_s[4][4];
#pragma unroll
    for (int a = 0; a < 4; a++)
#pragma unroll
        for (int b2 = 0; b2 < 4; b2++) acc_s[a][b2] = 0.f;

    const float* xn = x + (n * 300 + chunk * 10) * 1600;

    // --- mma decode: mt = wid>>1 (rows), chunks (wid&1)+2*c3 (16 cols each) ---
    const int mt = wid >> 1;
    const int ncb = wid & 1;
    const int arow = mt * 16 + ((lane >> 3) & 1) * 8 + (lane & 7);
    const unsigned aoff = (unsigned)(arow * 144 + (lane >> 4) * 16);
    const unsigned boff = (unsigned)((lane & 15) * 208 + (lane >> 4) * 16);
    const unsigned xhB = (unsigned)__cvta_generic_to_shared(Xh);
    const unsigned xlB = (unsigned)__cvta_generic_to_shared(Xl);
    const unsigned ghB = (unsigned)__cvta_generic_to_shared(Ghi);
    const unsigned glB = (unsigned)__cvta_generic_to_shared(Glo);
    const int crow = mt * 16 + (lane >> 2);
    const int ccol = 2 * (lane & 3);

    for (int step = 0; step < 5; ++step) {
        __syncthreads();
        {   // convert 2 t-tiles of X -> bf16 hi/lo, rows 0-49
            const float4* src = (const float4*)(xn + step * 3200);
            for (int e = tid; e < 800; e += 256) {
                float4 v = src[e];
                int r = e >> 4, c = (e & 15) * 4;
                __nv_bfloat16 h0 = __float2bfloat16_rn(v.x), h1 = __float2bfloat16_rn(v.y);
                __nv_bfloat16 h2 = __float2bfloat16_rn(v.z), h3 = __float2bfloat16_rn(v.w);
                Xh[r * 72 + c]     = h0; Xh[r * 72 + c + 1] = h1;
                Xh[r * 72 + c + 2] = h2; Xh[r * 72 + c + 3] = h3;
                Xl[r * 72 + c]     = __float2bfloat16_rn(v.x - __bfloat162float(h0));
                Xl[r * 72 + c + 1] = __float2bfloat16_rn(v.y - __bfloat162float(h1));
                Xl[r * 72 + c + 2] = __float2bfloat16_rn(v.z - __bfloat162float(h2));
                Xl[r * 72 + c + 3] = __float2bfloat16_rn(v.w - __bfloat162float(h3));
            }
        }
        __syncthreads();

        // --- E = X * G on tensor cores (all 8 warps, 6 n8-tiles each) ---
        {
            float acc[6][4];
#pragma unroll
            for (int i = 0; i < 6; ++i)
#pragma unroll
                for (int j = 0; j < 4; ++j) acc[i][j] = 0.f;

#pragma unroll
            for (int ks = 0; ks < 4; ++ks) {
                unsigned ahi[4], alo[4];
                ldsm_x4(ahi[0], ahi[1], ahi[2], ahi[3], xhB + aoff + ks * 32);
                ldsm_x4(alo[0], alo[1], alo[2], alo[3], xlB + aoff + ks * 32);
#pragma unroll
                for (int c3 = 0; c3 < 3; ++c3) {
                    const int ch = ncb + 2 * c3;
                    const unsigned kb = boff + (unsigned)(ks * 3328 + ch * 32);
                    unsigned bh[4], bl[4];
                    ldsm_x4t(bh[0], bh[1], bh[2], bh[3], ghB + kb);
                    ldsm_x4t(bl[0], bl[1], bl[2], bl[3], glB + kb);
                    float* a0 = acc[c3 * 2];
                    float* a1 = acc[c3 * 2 + 1];
                    mma_bf16(a0, ahi, bh[0], bh[1]);
                    mma_bf16(a0, ahi, bl[0], bl[1]);
                    mma_bf16(a0, alo, bh[0], bh[1]);
                    mma_bf16(a1, ahi, bh[2], bh[3]);
                    mma_bf16(a1, ahi, bl[2], bl[3]);
                    mma_bf16(a1, alo, bh[2], bh[3]);
                }
            }
            // fragment store: +bias (fp32), transpose into Qt/Kt i-major
#pragma unroll
            for (int c3 = 0; c3 < 3; ++c3) {
                const int ch = ncb + 2 * c3;
#pragma unroll
                for (int nt = 0; nt < 2; ++nt) {
                    const float* a = acc[c3 * 2 + nt];
                    const int col0 = ch * 16 + nt * 8 + ccol;
#pragma unroll
                    for (int rr = 0; rr < 2; ++rr) {
                        const int r = crow + rr * 8;
                        if (r < 50) {
                            const int t2 = (r >= 25);
                            const int v = r - t2 * 25;
#pragma unroll
                            for (int jj = 0; jj < 2; ++jj) {
                                const int j = col0 + jj;
                                const float val = a[rr * 2 + jj] + bs[j];
                                const int qk = (j >= 48);
                                const int jl = j - qk * 48;
                                float* eb = qk ? Kt : Qt;
                                eb[t2 * 1344 + (jl >> 4) * 448 + (jl & 15) * 28 + v] = val;
                            }
                        }
                    }
                }
            }
        }
        __syncthreads();

        // --- Score accumulation: S[k][4v][4w] += Q^T.K over i=16, 2 t's ---
        if (score_active) {
#pragma unroll
            for (int ti = 0; ti < 2; ++ti) {
                const float4* qv = (const float4*)(Qt + ti * 1344 + kq_s * 448 + vp_s * 4);
                const float4* kt = (const float4*)(Kt + ti * 1344 + kq_s * 448 + w4_s * 4);
#pragma unroll
                for (int i = 0; i < 16; ++i) {
                    float4 q  = qv[i * 7];
                    float4 kv = kt[i * 7];
                    acc_s[0][0] += q.x * kv.x; acc_s[0][1] += q.x * kv.y;
                    acc_s[0][2] += q.x * kv.z; acc_s[0][3] += q.x * kv.w;
                    acc_s[1][0] += q.y * kv.x; acc_s[1][1] += q.y * kv.y;
                    acc_s[1][2] += q.y * kv.z; acc_s[1][3] += q.y * kv.w;
                    acc_s[2][0] += q.z * kv.x; acc_s[2][1] += q.z * kv.y;
                    acc_s[2][2] += q.z * kv.z; acc_s[2][3] += q.z * kv.w;
                    acc_s[3][0] += q.w * kv.x; acc_s[3][1] += q.w * kv.y;
                    acc_s[3][2] += q.w * kv.z; acc_s[3][3] += q.w * kv.w;
                }
            }
        }
    }

    // --- write chunk partials (guards discard pad-lane garbage) ---
    if (score_active) {
        float* base = g_Spart + ((chunk * 3 + kq_s) * 64 + n) * 625;
#pragma unroll
        for (int vi = 0; vi < 4; ++vi) {
            int v = vp_s * 4 + vi;
            if (v < 25) {
#pragma unroll
                for (int j = 0; j < 4; ++j) {
                    int w = w4_s * 4 + j;
                    if (w < 25) base[v * 25 + w] = acc_s[vi][j];
                }
            }
        }
    }
}

// ---------------------------------------------------------------------------
// Kernel 2: reduce chunk partials, softmax, add A.
// ---------------------------------------------------------------------------
__global__ __launch_bounds__(128) void softmax_kernel(const float* __restrict__ A)
{
    __shared__ float S[625];
    const int b = blockIdx.x;
    const int kq = b / 64, n = b % 64;
    const int tid = threadIdx.x;

    for (int e = tid; e < 625; e += 128) {
        float s = 0.f;
        int base = ((kq * 64) + n) * 625 + e;
#pragma unroll 6
        for (int ch = 0; ch < 30; ++ch) s += g_Spart[ch * 120000 + base];
        S[e] = s;
    }
    __syncthreads();

    if (tid < 25) {
        const int v = tid;
        float m = -1e30f;
#pragma unroll
        for (int w = 0; w < 25; ++w) {
            float z = S[v * 25 + w] * SCALE_D;
            m = fmaxf(m, z);
        }
        float p[25];
        float sum = 0.f;
#pragma unroll
        for (int w = 0; w < 25; ++w) {
            p[w] = expf(S[v * 25 + w] * SCALE_D - m);
            sum += p[w];
        }
        float inv = 1.f / sum;
        float* dst = g_Aad + ((kq * 64) + n) * 625 + v * 25;
        const float* Ab = A + kq * 625 + v * 25;
#pragma unroll
        for (int w = 0; w < 25; ++w) dst[w] = Ab[w] + p[w] * inv;
    }
}

// ---------------------------------------------------------------------------
// Kernel 3: main path, pipelined tensor-H (EXACT copy of the R11 version).
// ---------------------------------------------------------------------------
#define SM_WHI   0
#define SM_WLO   25600
#define SM_XBUF  51200
#define SM_HS    69632
#define SM_AS    89232
#define SM_STG   97632
#define SM_CSUM  104800
#define SM_BSM   105120
#define SM_TOTAL 105888

__global__ __launch_bounds__(256) void main_kernel(
    const float* __restrict__ x, const float* __restrict__ W,
    const float* __restrict__ b, float* __restrict__ y)
{
    extern __shared__ char smraw[];
    __nv_bfloat16* Whi = (__nv_bfloat16*)(smraw + SM_WHI);
    __nv_bfloat16* Wlo = (__nv_bfloat16*)(smraw + SM_WLO);
    float* Hs   = (float*)(smraw + SM_HS);
    float* As   = (float*)(smraw + SM_AS);
    float* stg  = (float*)(smraw + SM_STG);
    float* csum = (float*)(smraw + SM_CSUM);
    float* bsm  = (float*)(smraw + SM_BSM);

    const int tid = threadIdx.x;
    const int lane = tid & 31;
    const int wid = tid >> 5;
    const int n = blockIdx.y;
    const int tc = blockIdx.x;

    for (int e = tid; e < 12288; e += 256) {
        float wv = W[e];
        __nv_bfloat16 hi = __float2bfloat16_rn(wv);
        __nv_bfloat16 lo = __float2bfloat16_rn(wv - __bfloat162float(hi));
        int c = e / 192, f = e % 192;
        Whi[c * 200 + f] = hi;
        Wlo[c * 200 + f] = lo;
    }
    for (int e = tid; e < 1008; e += 256) {
        int buf = e / 504, r = 25 + (e % 504) / 72, c = e % 72;
        __nv_bfloat16* Xh = (__nv_bfloat16*)(smraw + SM_XBUF + buf * 9216);
        __nv_bfloat16* Xl = Xh + 2304;
        Xh[r * 72 + c] = __float2bfloat16_rn(0.f);
        Xl[r * 72 + c] = __float2bfloat16_rn(0.f);
    }
    for (int e = tid; e < 1875; e += 256) {
        int k = e / 625, rem = e % 625;
        int v = rem / 25, w = rem % 25;
        As[k * 700 + v * 28 + w] = g_Aad[(k * 64 + n) * 625 + rem];
    }
    for (int e = tid; e < 225; e += 256) {
        int k = e / 75, r = e % 75;
        As[k * 700 + (r / 3) * 28 + 25 + (r % 3)] = 0.f;
    }
    if (tid < 192) bsm[tid] = b[tid];
    __syncthreads();

    if (tid < 75) {
        int k = tid / 25, w = tid % 25;
        float s = 0.f;
#pragma unroll
        for (int v = 0; v < 25; ++v) s += As[k * 700 + v * 28 + w];
        csum[tid] = s;
    }
    __syncthreads();

    const int vh    = (tid < 224) ? tid / 112 : 0;
    const int ytile = (tid < 224) ? tid % 112 : 0;
    const int w4 = ytile / 16;
    const int f4 = ytile % 16;
    u64 yb[4][2];
    if (tid < 224) {
#pragma unroll
        for (int j = 0; j < 4; ++j) {
            int w = w4 * 4 + j;
            if (vh == 0 && w < 25) {
#pragma unroll
                for (int p = 0; p < 2; ++p) {
                    int f0 = f4 * 4 + 2 * p;
                    float v0 = bsm[f0]     * csum[w] + bsm[64 + f0]     * csum[25 + w]
                             + bsm[128 + f0]     * csum[50 + w];
                    float v1 = bsm[f0 + 1] * csum[w] + bsm[64 + f0 + 1] * csum[25 + w]
                             + bsm[128 + f0 + 1] * csum[50 + w];
                    yb[j][p] = pk2(v0, v1);
                }
            } else { yb[j][0] = 0ull; yb[j][1] = 0ull; }
        }
    }

    {
        const float4* src = (const float4*)(x + (n * 300 + tc * 12) * 1600);
        __nv_bfloat16* Xh = (__nv_bfloat16*)(smraw + SM_XBUF);
        __nv_bfloat16* Xl = Xh + 2304;
        for (int e = tid; e < 400; e += 256) {
            float4 v = src[e];
            int r = e >> 4, c = (e & 15) * 4;
            __nv_bfloat16 h0 = __float2bfloat16_rn(v.x), h1 = __float2bfloat16_rn(v.y);
            __nv_bfloat16 h2 = __float2bfloat16_rn(v.z), h3 = __float2bfloat16_rn(v.w);
            Xh[r * 72 + c]     = h0; Xh[r * 72 + c + 1] = h1;
            Xh[r * 72 + c + 2] = h2; Xh[r * 72 + c + 3] = h3;
            Xl[r * 72 + c]     = __float2bfloat16_rn(v.x - __bfloat162float(h0));
            Xl[r * 72 + c + 1] = __float2bfloat16_rn(v.y - __bfloat162float(h1));
            Xl[r * 72 + c + 2] = __float2bfloat16_rn(v.z - __bfloat162float(h2));
            Xl[r * 72 + c + 3] = __float2bfloat16_rn(v.w - __bfloat162float(h3));
        }
    }
    __syncthreads();

    const int mt = wid >> 2;
    const int nb = wid & 3;
    const int arow = mt * 16 + ((lane >> 3) & 1) * 8 + (lane & 7);
    const unsigned aoff = (unsigned)(arow * 144 + (lane >> 4) * 16);
    const unsigned boff = (unsigned)((lane & 15) * 400 + (lane >> 4) * 16);
    const unsigned whiB = (unsigned)__cvta_generic_to_shared(Whi);
    const unsigned wloB = (unsigned)__cvta_generic_to_shared(Wlo);
    const unsigned xbufB = (unsigned)__cvta_generic_to_shared(smraw + SM_XBUF);

    for (int it = 0; it < 12; ++it) {
        const int t = tc * 12 + it;
        const unsigned xhiB = xbufB + (unsigned)((it & 1) * 9216);
        const unsigned xloB = xhiB + 4608;

        {
            float acc[6][4];
#pragma unroll
            for (int i = 0; i < 6; ++i)
#pragma unroll
                for (int j = 0; j < 4; ++j) acc[i][j] = 0.f;

#pragma unroll
            for (int ks = 0; ks < 4; ++ks) {
                unsigned ahi[4], alo[4];
                ldsm_x4(ahi[0], ahi[1], ahi[2], ahi[3], xhiB + aoff + ks * 32);
                ldsm_x4(alo[0], alo[1], alo[2], alo[3], xloB + aoff + ks * 32);
#pragma unroll
                for (int c3 = 0; c3 < 3; ++c3) {
                    const int chunk = nb + 4 * c3;
                    const unsigned kb = boff + (unsigned)(ks * 6400 + chunk * 32);
                    unsigned bh[4], bl[4];
                    ldsm_x4t(bh[0], bh[1], bh[2], bh[3], whiB + kb);
                    ldsm_x4t(bl[0], bl[1], bl[2], bl[3], wloB + kb);
                    float* a0 = acc[c3 * 2];
                    float* a1 = acc[c3 * 2 + 1];
                    mma_bf16(a0, ahi, bh[0], bh[1]);
                    mma_bf16(a0, ahi, bl[0], bl[1]);
                    mma_bf16(a0, alo, bh[0], bh[1]);
                    mma_bf16(a1, ahi, bh[2], bh[3]);
                    mma_bf16(a1, ahi, bl[2], bl[3]);
                    mma_bf16(a1, alo, bh[2], bh[3]);
                }
            }
            const int crow = mt * 16 + (lane >> 2);
            const int ccol = 2 * (lane & 3);
            const bool s0ok = (crow < 25);
            const bool s1ok = (crow + 8 < 25);
#pragma unroll
            for (int c3 = 0; c3 < 3; ++c3) {
#pragma unroll
                for (int nt = 0; nt < 2; ++nt) {
                    const int n0 = (nb + 4 * c3) * 16 + nt * 8;
                    const float* a = acc[c3 * 2 + nt];
                    if (s0ok) *(float2*)&Hs[crow * 196 + n0 + ccol]       = make_float2(a[0], a[1]);
                    if (s1ok) *(float2*)&Hs[(crow + 8) * 196 + n0 + ccol] = make_float2(a[2], a[3]);
                }
            }
        }
        __syncthreads();

        u64 s2[4][2];
        if (tid < 224) {
#pragma unroll
            for (int j = 0; j < 4; ++j) { s2[j][0] = yb[j][0]; s2[j][1] = yb[j][1]; }
            const int vbeg = vh ? 13 : 0;
            const int vend = vh ? 25 : 13;
            const ulonglong2* H2 = (const ulonglong2*)Hs;
#pragma unroll
            for (int k = 0; k < 3; ++k) {
                const float* Ab = As + k * 700 + w4 * 4;
                const int hidx = k * 16 + f4;
                for (int v = vbeg; v < vend; ++v) {
                    float4 a = *(const float4*)(Ab + v * 28);
                    ulonglong2 h = H2[v * 49 + hidx];
                    u64 d0 = pk2(a.x, a.x), d1 = pk2(a.y, a.y);
                    u64 d2 = pk2(a.z, a.z), d3 = pk2(a.w, a.w);
                    fma2(s2[0][0], d0, h.x); fma2(s2[0][1], d0, h.y);
                    fma2(s2[1][0], d1, h.x); fma2(s2[1][1], d1, h.y);
                    fma2(s2[2][0], d2, h.x); fma2(s2[2][1], d2, h.y);
                    fma2(s2[3][0], d3, h.x); fma2(s2[3][1], d3, h.y);
                }
            }
            if (vh == 1) {
                u64* st = (u64*)stg;
#pragma unroll
                for (int j = 0; j < 4; ++j) {
                    st[ytile * 8 + j * 2]     = s2[j][0];
                    st[ytile * 8 + j * 2 + 1] = s2[j][1];
                }
            }
        } else if (wid == 7 && it < 11) {
            const float4* src = (const float4*)(x + (n * 300 + t + 1) * 1600);
            __nv_bfloat16* Xh = (__nv_bfloat16*)(smraw + SM_XBUF + ((it + 1) & 1) * 9216);
            __nv_bfloat16* Xl = Xh + 2304;
            for (int e = lane; e < 400; e += 32) {
                float4 v = src[e];
                int r = e >> 4, c = (e & 15) * 4;
                __nv_bfloat16 h0 = __float2bfloat16_rn(v.x), h1 = __float2bfloat16_rn(v.y);
                __nv_bfloat16 h2 = __float2bfloat16_rn(v.z), h3 = __float2bfloat16_rn(v.w);
                Xh[r * 72 + c]     = h0; Xh[r * 72 + c + 1] = h1;
                Xh[r * 72 + c + 2] = h2; Xh[r * 72 + c + 3] = h3;
                Xl[r * 72 + c]     = __float2bfloat16_rn(v.x - __bfloat162float(h0));
                Xl[r * 72 + c + 1] = __float2bfloat16_rn(v.y - __bfloat162float(h1));
                Xl[r * 72 + c + 2] = __float2bfloat16_rn(v.z - __bfloat162float(h2));
                Xl[r * 72 + c + 3] = __float2bfloat16_rn(v.w - __bfloat162float(h3));
            }
        }
        __syncthreads();

        if (tid < 112) {
            const u64* st = (const u64*)stg;
            float4* yout = (float4*)(y + (n * 300 + t) * 1600);
#pragma unroll
            for (int j = 0; j < 4; ++j) {
                int w = w4 * 4 + j;
                if (w < 25) {
                    float p0, p1, p2, p3, o0, o1, o2, o3;
                    up2(s2[j][0], p0, p1);
                    up2(s2[j][1], p2, p3);
                    up2(st[ytile * 8 + j * 2],     o0, o1);
                    up2(st[ytile * 8 + j * 2 + 1], o2, o3);
                    yout[w * 16 + f4] = make_float4(p0 + o0, p1 + o1, p2 + o2, p3 + o3);
                }
            }
        }
    }
}

// ---------------------------------------------------------------------------
extern "C" void kernel_launch(void* const* d_in, const int* in_sizes, int n_in,
                              void* d_out, int out_size)
{
    const float* x  = (const float*)d_in[0];
    const float* A  = (const float*)d_in[1];
    const float* W  = (const float*)d_in[2];
    const float* b  = (const float*)d_in[3];
    const float* Wq = (const float*)d_in[4];
    const float* bq = (const float*)d_in[5];
    const float* Wk = (const float*)d_in[6];
    const float* bk = (const float*)d_in[7];
    float* y = (float*)d_out;

    cudaFuncSetAttribute(score_kernel, cudaFuncAttributeMaxDynamicSharedMemorySize, SC_TOTAL);
    cudaFuncSetAttribute(main_kernel,  cudaFuncAttributeMaxDynamicSharedMemorySize, SM_TOTAL);

    score_kernel<<<dim3(30, 64), 256, SC_TOTAL>>>(x, Wq, bq, Wk, bk);
    softmax_kernel<<<192, 128>>>(A);
    main_kernel<<<dim3(25, 64), 256, SM_TOTAL>>>(x, W, b, y);
}